// round 7
// baseline (speedup 1.0000x reference)
#include <cuda_runtime.h>
#include <math.h>

// ---------------------------------------------------------------------------
// Scratch: node state and aggregation buffer. N = 1,000,000 fits in 1<<20.
// ---------------------------------------------------------------------------
#define MAXN (1 << 20)
__device__ float2 g_xn[MAXN];
__device__ float2 g_agg[MAXN];
__device__ int    g_idx64;   // 1 if edge_index is int64, 0 if int32

#define EPSF 1e-15f

__device__ __forceinline__ void red_add_f32x2(float2* p, float vx, float vy) {
    asm volatile("red.global.add.v2.f32 [%0], {%1, %2};"
                 :: "l"(p), "f"(vx), "f"(vy)
                 : "memory");
}

// ---------------------------------------------------------------------------
// Kernel 1: normalize x into g_xn (2 nodes/thread via float4), zero g_agg.
// Block 0 also detects the index dtype (int32 vs int64): interpret the first
// 2048 8-byte words as int64; any value outside [0,N) => data is int32.
// ---------------------------------------------------------------------------
__global__ void k_init(const float4* __restrict__ x, int Npairs, int N,
                       const long long* __restrict__ ei, long long n_words) {
    int i = blockIdx.x * blockDim.x + threadIdx.x;
    if (i < Npairs) {
        float4 v = x[i];   // two nodes: (v.x,v.y) and (v.z,v.w)
        float inv0 = 1.0f / (sqrtf(v.x * v.x + v.y * v.y) + EPSF);
        float inv1 = 1.0f / (sqrtf(v.z * v.z + v.w * v.w) + EPSF);
        ((float4*)g_xn)[i] = make_float4(v.x * inv0, v.y * inv0,
                                         v.z * inv1, v.w * inv1);
        ((float4*)g_agg)[i] = make_float4(0.f, 0.f, 0.f, 0.f);
    }
    if (blockIdx.x == 0) {
        __shared__ int bad;
        if (threadIdx.x == 0) bad = 0;
        __syncthreads();
        long long lim = n_words < 2048 ? n_words : 2048;
        int local_bad = 0;
        for (long long w = threadIdx.x; w < lim; w += blockDim.x) {
            long long v = ei[w];
            if (v < 0 || v >= (long long)N) local_bad = 1;
        }
        if (local_bad) bad = 1;
        __syncthreads();
        if (threadIdx.x == 0) g_idx64 = bad ? 0 : 1;
    }
}

// ---------------------------------------------------------------------------
// Kernel 2: edge scatter: g_agg[dst[e]] += g_xn[src[e]].
// R3-measured-best shape: grid-stride, 8192 blocks x 256 threads, 4 edges per
// iteration, int4/longlong2 coalesced index loads, 4 independent gathers
// batched before the 4 reds. This kernel runs at the joint LTS-sector /
// L1tex-wavefront floor (~2 wavefronts + ~2 x 32B sectors per edge).
// ---------------------------------------------------------------------------
__global__ void __launch_bounds__(256) k_scatter(const void* __restrict__ eiv, long long E) {
    long long tid    = (long long)blockIdx.x * blockDim.x + threadIdx.x;
    long long stride = (long long)gridDim.x * blockDim.x;

    if (g_idx64 == 0) {
        const int* src = (const int*)eiv;
        const int* dst = src + E;
        long long quads = E >> 2;
        for (long long q = tid; q < quads; q += stride) {
            int4 s = __ldg((const int4*)(src + 4 * q));
            int4 d = __ldg((const int4*)(dst + 4 * q));
            float2 v0 = g_xn[s.x];
            float2 v1 = g_xn[s.y];
            float2 v2 = g_xn[s.z];
            float2 v3 = g_xn[s.w];
            red_add_f32x2(&g_agg[d.x], v0.x, v0.y);
            red_add_f32x2(&g_agg[d.y], v1.x, v1.y);
            red_add_f32x2(&g_agg[d.z], v2.x, v2.y);
            red_add_f32x2(&g_agg[d.w], v3.x, v3.y);
        }
        if (tid == 0) {
            for (long long e = quads * 4; e < E; e++) {
                float2 v = g_xn[src[e]];
                red_add_f32x2(&g_agg[dst[e]], v.x, v.y);
            }
        }
    } else {
        const long long* src = (const long long*)eiv;
        const long long* dst = src + E;
        long long pairs = E >> 1;
        for (long long p = tid; p < pairs; p += stride) {
            longlong2 s = __ldg((const longlong2*)(src + 2 * p));
            longlong2 d = __ldg((const longlong2*)(dst + 2 * p));
            float2 v0 = g_xn[(int)s.x];
            float2 v1 = g_xn[(int)s.y];
            red_add_f32x2(&g_agg[(int)d.x], v0.x, v0.y);
            red_add_f32x2(&g_agg[(int)d.y], v1.x, v1.y);
        }
        if (tid == 0 && (E & 1LL)) {
            long long e = E - 1;
            float2 v = g_xn[(int)src[e]];
            red_add_f32x2(&g_agg[(int)dst[e]], v.x, v.y);
        }
    }
}

// ---------------------------------------------------------------------------
// Kernel 3: mid-iteration: y = relu(agg @ W); renormalize; zero g_agg.
// 2 nodes per thread via float4.
// ---------------------------------------------------------------------------
__global__ void k_mid(const float* __restrict__ W, int Npairs) {
    int i = blockIdx.x * blockDim.x + threadIdx.x;
    if (i >= Npairs) return;
    float w00 = W[0], w01 = W[1], w10 = W[2], w11 = W[3];
    float4 a = ((const float4*)g_agg)[i];
    float y0 = fmaxf(fmaf(a.y, w10, a.x * w00), 0.0f);
    float y1 = fmaxf(fmaf(a.y, w11, a.x * w01), 0.0f);
    float y2 = fmaxf(fmaf(a.w, w10, a.z * w00), 0.0f);
    float y3 = fmaxf(fmaf(a.w, w11, a.z * w01), 0.0f);
    float inv0 = 1.0f / (sqrtf(y0 * y0 + y1 * y1) + EPSF);
    float inv1 = 1.0f / (sqrtf(y2 * y2 + y3 * y3) + EPSF);
    ((float4*)g_xn)[i] = make_float4(y0 * inv0, y1 * inv0, y2 * inv1, y3 * inv1);
    ((float4*)g_agg)[i] = make_float4(0.f, 0.f, 0.f, 0.f);
}

// ---------------------------------------------------------------------------
// Kernel 4: final: y = relu(agg @ W); out = sigmoid(y . final_weight).
// 2 nodes per thread.
// ---------------------------------------------------------------------------
__global__ void k_final(const float* __restrict__ W,
                        const float* __restrict__ fw,
                        float2* __restrict__ out, int Npairs) {
    int i = blockIdx.x * blockDim.x + threadIdx.x;
    if (i >= Npairs) return;
    float w00 = W[0], w01 = W[1], w10 = W[2], w11 = W[3];
    float f0 = fw[0], f1 = fw[1];
    float4 a = ((const float4*)g_agg)[i];
    float y0 = fmaxf(fmaf(a.y, w10, a.x * w00), 0.0f);
    float y1 = fmaxf(fmaf(a.y, w11, a.x * w01), 0.0f);
    float y2 = fmaxf(fmaf(a.w, w10, a.z * w00), 0.0f);
    float y3 = fmaxf(fmaf(a.w, w11, a.z * w01), 0.0f);
    float s0 = fmaf(y1, f1, y0 * f0);
    float s1 = fmaf(y3, f1, y2 * f0);
    out[i] = make_float2(1.0f / (1.0f + expf(-s0)),
                         1.0f / (1.0f + expf(-s1)));
}

// ---------------------------------------------------------------------------
// Launch: init(+detect) -> scatter -> mid -> scatter -> final.
// Graph-capturable, allocation-free, no syncs.
// ---------------------------------------------------------------------------
extern "C" void kernel_launch(void* const* d_in, const int* in_sizes, int n_in,
                              void* d_out, int out_size) {
    const float* x  = (const float*)d_in[0];
    const void*  ei = (const void*)d_in[1];
    const float* W  = (const float*)d_in[2];
    const float* fw = (const float*)d_in[3];
    float2* out = (float2*)d_out;

    int N = in_sizes[0] / 2;          // N is even (1,000,000)
    int Npairs = N / 2;
    long long E = (long long)in_sizes[1] / 2;

    const int TB = 256;
    int nb_pairs = (Npairs + TB - 1) / TB;
    const int SCATTER_BLOCKS = 8192;   // R3-measured-best grid shape

    k_init<<<nb_pairs, TB>>>((const float4*)x, Npairs, N,
                             (const long long*)ei, E);
    k_scatter<<<SCATTER_BLOCKS, TB>>>(ei, E);
    k_mid<<<nb_pairs, TB>>>(W, Npairs);
    k_scatter<<<SCATTER_BLOCKS, TB>>>(ei, E);
    k_final<<<nb_pairs, TB>>>(W, fw, out, Npairs);

    (void)n_in; (void)out_size;
}

// round 8
// speedup vs baseline: 1.0245x; 1.0245x over previous
#include <cuda_runtime.h>
#include <math.h>

// ---------------------------------------------------------------------------
// Scratch: node state and aggregation buffer. N = 1,000,000 fits in 1<<20.
// ---------------------------------------------------------------------------
#define MAXN (1 << 20)
__device__ float2 g_xn[MAXN];
__device__ float2 g_agg[MAXN];
__device__ int    g_idx64;   // 1 if edge_index is int64, 0 if int32

#define EPSF 1e-15f

__device__ __forceinline__ void red_add_f32x2(float2* p, float vx, float vy) {
    asm volatile("red.global.add.v2.f32 [%0], {%1, %2};"
                 :: "l"(p), "f"(vx), "f"(vy)
                 : "memory");
}

// L2-only 8-byte gather (random access; skip the L1 stage).
__device__ __forceinline__ float2 ldcg_f2(const float2* p) {
    float2 r;
    asm volatile("ld.global.cg.v2.f32 {%0, %1}, [%2];"
                 : "=f"(r.x), "=f"(r.y) : "l"(p));
    return r;
}

// ---------------------------------------------------------------------------
// Kernel 1: normalize x into g_xn (2 nodes/thread via float4), zero g_agg.
// Block 0 also detects the index dtype (int32 vs int64): interpret the first
// 2048 8-byte words as int64; any value outside [0,N) => data is int32.
// ---------------------------------------------------------------------------
__global__ void k_init(const float4* __restrict__ x, int Npairs, int N,
                       const long long* __restrict__ ei, long long n_words) {
    int i = blockIdx.x * blockDim.x + threadIdx.x;
    if (i < Npairs) {
        float4 v = x[i];   // two nodes: (v.x,v.y) and (v.z,v.w)
        float inv0 = 1.0f / (sqrtf(v.x * v.x + v.y * v.y) + EPSF);
        float inv1 = 1.0f / (sqrtf(v.z * v.z + v.w * v.w) + EPSF);
        ((float4*)g_xn)[i] = make_float4(v.x * inv0, v.y * inv0,
                                         v.z * inv1, v.w * inv1);
        ((float4*)g_agg)[i] = make_float4(0.f, 0.f, 0.f, 0.f);
    }
    if (blockIdx.x == 0) {
        __shared__ int bad;
        if (threadIdx.x == 0) bad = 0;
        __syncthreads();
        long long lim = n_words < 2048 ? n_words : 2048;
        int local_bad = 0;
        for (long long w = threadIdx.x; w < lim; w += blockDim.x) {
            long long v = ei[w];
            if (v < 0 || v >= (long long)N) local_bad = 1;
        }
        if (local_bad) bad = 1;
        __syncthreads();
        if (threadIdx.x == 0) g_idx64 = bad ? 0 : 1;
    }
}

// ---------------------------------------------------------------------------
// Kernel 2: edge scatter: g_agg[dst[e]] += g_xn[src[e]].
// Measured-best configuration (R6: 233.98us, occ 82%, regs 32):
// one quad (4 edges) per thread, no grid-stride loop; __ldcs streamed index
// loads; ld.global.cg (L2-only) gathers; 4 independent gathers batched
// before the 4 reds. Runs at the joint LTS-sector / L1tex-wavefront floor.
// ---------------------------------------------------------------------------
__global__ void __launch_bounds__(256) k_scatter(const void* __restrict__ eiv, long long E) {
    long long q = (long long)blockIdx.x * blockDim.x + threadIdx.x;
    long long quads = E >> 2;

    if (g_idx64 == 0) {
        const int* src = (const int*)eiv;
        const int* dst = src + E;
        if (q < quads) {
            int4 s = __ldcs((const int4*)(src + 4 * q));
            int4 d = __ldcs((const int4*)(dst + 4 * q));
            float2 v0 = ldcg_f2(&g_xn[s.x]);
            float2 v1 = ldcg_f2(&g_xn[s.y]);
            float2 v2 = ldcg_f2(&g_xn[s.z]);
            float2 v3 = ldcg_f2(&g_xn[s.w]);
            red_add_f32x2(&g_agg[d.x], v0.x, v0.y);
            red_add_f32x2(&g_agg[d.y], v1.x, v1.y);
            red_add_f32x2(&g_agg[d.z], v2.x, v2.y);
            red_add_f32x2(&g_agg[d.w], v3.x, v3.y);
        }
        if (q == 0) {
            for (long long e = quads * 4; e < E; e++) {
                float2 v = ldcg_f2(&g_xn[src[e]]);
                red_add_f32x2(&g_agg[dst[e]], v.x, v.y);
            }
        }
    } else {
        const long long* src = (const long long*)eiv;
        const long long* dst = src + E;
        if (q < quads) {
            longlong2 s0 = __ldcs((const longlong2*)(src + 4 * q));
            longlong2 s1 = __ldcs((const longlong2*)(src + 4 * q) + 1);
            longlong2 d0 = __ldcs((const longlong2*)(dst + 4 * q));
            longlong2 d1 = __ldcs((const longlong2*)(dst + 4 * q) + 1);
            float2 v0 = ldcg_f2(&g_xn[(int)s0.x]);
            float2 v1 = ldcg_f2(&g_xn[(int)s0.y]);
            float2 v2 = ldcg_f2(&g_xn[(int)s1.x]);
            float2 v3 = ldcg_f2(&g_xn[(int)s1.y]);
            red_add_f32x2(&g_agg[(int)d0.x], v0.x, v0.y);
            red_add_f32x2(&g_agg[(int)d0.y], v1.x, v1.y);
            red_add_f32x2(&g_agg[(int)d1.x], v2.x, v2.y);
            red_add_f32x2(&g_agg[(int)d1.y], v3.x, v3.y);
        }
        if (q == 0) {
            for (long long e = quads * 4; e < E; e++) {
                float2 v = ldcg_f2(&g_xn[(int)src[e]]);
                red_add_f32x2(&g_agg[(int)dst[e]], v.x, v.y);
            }
        }
    }
}

// ---------------------------------------------------------------------------
// Kernel 3: mid-iteration: y = relu(agg @ W); renormalize; zero g_agg.
// 2 nodes per thread via float4.
// ---------------------------------------------------------------------------
__global__ void k_mid(const float* __restrict__ W, int Npairs) {
    int i = blockIdx.x * blockDim.x + threadIdx.x;
    if (i >= Npairs) return;
    float w00 = W[0], w01 = W[1], w10 = W[2], w11 = W[3];
    float4 a = ((const float4*)g_agg)[i];
    float y0 = fmaxf(fmaf(a.y, w10, a.x * w00), 0.0f);
    float y1 = fmaxf(fmaf(a.y, w11, a.x * w01), 0.0f);
    float y2 = fmaxf(fmaf(a.w, w10, a.z * w00), 0.0f);
    float y3 = fmaxf(fmaf(a.w, w11, a.z * w01), 0.0f);
    float inv0 = 1.0f / (sqrtf(y0 * y0 + y1 * y1) + EPSF);
    float inv1 = 1.0f / (sqrtf(y2 * y2 + y3 * y3) + EPSF);
    ((float4*)g_xn)[i] = make_float4(y0 * inv0, y1 * inv0, y2 * inv1, y3 * inv1);
    ((float4*)g_agg)[i] = make_float4(0.f, 0.f, 0.f, 0.f);
}

// ---------------------------------------------------------------------------
// Kernel 4: final: y = relu(agg @ W); out = sigmoid(y . final_weight).
// 2 nodes per thread.
// ---------------------------------------------------------------------------
__global__ void k_final(const float* __restrict__ W,
                        const float* __restrict__ fw,
                        float2* __restrict__ out, int Npairs) {
    int i = blockIdx.x * blockDim.x + threadIdx.x;
    if (i >= Npairs) return;
    float w00 = W[0], w01 = W[1], w10 = W[2], w11 = W[3];
    float f0 = fw[0], f1 = fw[1];
    float4 a = ((const float4*)g_agg)[i];
    float y0 = fmaxf(fmaf(a.y, w10, a.x * w00), 0.0f);
    float y1 = fmaxf(fmaf(a.y, w11, a.x * w01), 0.0f);
    float y2 = fmaxf(fmaf(a.w, w10, a.z * w00), 0.0f);
    float y3 = fmaxf(fmaf(a.w, w11, a.z * w01), 0.0f);
    float s0 = fmaf(y1, f1, y0 * f0);
    float s1 = fmaf(y3, f1, y2 * f0);
    out[i] = make_float2(1.0f / (1.0f + expf(-s0)),
                         1.0f / (1.0f + expf(-s1)));
}

// ---------------------------------------------------------------------------
// Launch: init(+detect) -> scatter -> mid -> scatter -> final.
// Graph-capturable, allocation-free, no syncs.
// ---------------------------------------------------------------------------
extern "C" void kernel_launch(void* const* d_in, const int* in_sizes, int n_in,
                              void* d_out, int out_size) {
    const float* x  = (const float*)d_in[0];
    const void*  ei = (const void*)d_in[1];
    const float* W  = (const float*)d_in[2];
    const float* fw = (const float*)d_in[3];
    float2* out = (float2*)d_out;

    int N = in_sizes[0] / 2;          // N is even (1,000,000)
    int Npairs = N / 2;
    long long E = (long long)in_sizes[1] / 2;
    long long quads = E >> 2;

    const int TB = 256;
    int nb_pairs = (Npairs + TB - 1) / TB;
    int nb_scatter = (int)((quads + TB - 1) / TB);   // one quad per thread

    k_init<<<nb_pairs, TB>>>((const float4*)x, Npairs, N,
                             (const long long*)ei, E);
    k_scatter<<<nb_scatter, TB>>>(ei, E);
    k_mid<<<nb_pairs, TB>>>(W, Npairs);
    k_scatter<<<nb_scatter, TB>>>(ei, E);
    k_final<<<nb_pairs, TB>>>(W, fw, out, Npairs);

    (void)n_in; (void)out_size;
}

// round 9
// speedup vs baseline: 1.0413x; 1.0163x over previous
#include <cuda_runtime.h>
#include <math.h>

// ---------------------------------------------------------------------------
// Scratch: node state and aggregation buffer. N = 1,000,000 fits in 1<<20.
// ---------------------------------------------------------------------------
#define MAXN (1 << 20)
__device__ float2 g_xn[MAXN];
__device__ float2 g_agg[MAXN];
__device__ int    g_idx64;   // 1 if edge_index is int64, 0 if int32

#define EPSF 1e-15f

// PDL (programmatic dependent launch) primitives, sm_90+.
// wait: block until the predecessor grid's memory is visible.
// launch_dependents: allow the dependent grid to begin launching.
#define PDL_WAIT()    asm volatile("griddepcontrol.wait;" ::: "memory")
#define PDL_TRIGGER() asm volatile("griddepcontrol.launch_dependents;" ::: "memory")

__device__ __forceinline__ void red_add_f32x2(float2* p, float vx, float vy) {
    asm volatile("red.global.add.v2.f32 [%0], {%1, %2};"
                 :: "l"(p), "f"(vx), "f"(vy)
                 : "memory");
}

// L2-only 8-byte gather (random access; skip the L1 stage).
__device__ __forceinline__ float2 ldcg_f2(const float2* p) {
    float2 r;
    asm volatile("ld.global.cg.v2.f32 {%0, %1}, [%2];"
                 : "=f"(r.x), "=f"(r.y) : "l"(p));
    return r;
}

// ---------------------------------------------------------------------------
// Kernel 1: normalize x into g_xn (2 nodes/thread via float4), zero g_agg.
// Block 0 also detects the index dtype (int32 vs int64).
// ---------------------------------------------------------------------------
__global__ void k_init(const float4* __restrict__ x, int Npairs, int N,
                       const long long* __restrict__ ei, long long n_words) {
    int i = blockIdx.x * blockDim.x + threadIdx.x;
    if (i < Npairs) {
        float4 v = x[i];   // two nodes: (v.x,v.y) and (v.z,v.w)
        float inv0 = 1.0f / (sqrtf(v.x * v.x + v.y * v.y) + EPSF);
        float inv1 = 1.0f / (sqrtf(v.z * v.z + v.w * v.w) + EPSF);
        ((float4*)g_xn)[i] = make_float4(v.x * inv0, v.y * inv0,
                                         v.z * inv1, v.w * inv1);
        ((float4*)g_agg)[i] = make_float4(0.f, 0.f, 0.f, 0.f);
    }
    if (blockIdx.x == 0) {
        __shared__ int bad;
        if (threadIdx.x == 0) bad = 0;
        __syncthreads();
        long long lim = n_words < 2048 ? n_words : 2048;
        int local_bad = 0;
        for (long long w = threadIdx.x; w < lim; w += blockDim.x) {
            long long v = ei[w];
            if (v < 0 || v >= (long long)N) local_bad = 1;
        }
        if (local_bad) bad = 1;
        __syncthreads();
        if (threadIdx.x == 0) g_idx64 = bad ? 0 : 1;
    }
    PDL_TRIGGER();
}

// ---------------------------------------------------------------------------
// Kernel 2: edge scatter: g_agg[dst[e]] += g_xn[src[e]].
// Measured-best shape (R6/R8: 233.98us, occ 82%, regs 32): one quad per
// thread, __ldcs index loads, L2-only gathers, 4 gathers batched before reds.
// PDL: prefetch the index quad (input data, never written by us) BEFORE the
// dependency wait, so the 256MB index stream starts while the predecessor
// kernel drains. g_idx64 / g_xn / g_agg are only touched after PDL_WAIT.
// ---------------------------------------------------------------------------
__global__ void __launch_bounds__(256) k_scatter(const void* __restrict__ eiv, long long E) {
    long long q = (long long)blockIdx.x * blockDim.x + threadIdx.x;
    long long quads = E >> 2;

    // Prologue: prefetch assuming int32 layout (the actual case). For int64
    // data these addresses are still in-bounds reads of the same buffer; the
    // values are simply discarded by the int64 branch below.
    int4 s = make_int4(0, 0, 0, 0), d = make_int4(0, 0, 0, 0);
    if (q < quads) {
        const int* src32 = (const int*)eiv;
        s = __ldcs((const int4*)(src32 + 4 * q));
        d = __ldcs((const int4*)(src32 + E + 4 * q));
    }

    PDL_WAIT();

    if (g_idx64 == 0) {
        const int* src = (const int*)eiv;
        const int* dst = src + E;
        if (q < quads) {
            float2 v0 = ldcg_f2(&g_xn[s.x]);
            float2 v1 = ldcg_f2(&g_xn[s.y]);
            float2 v2 = ldcg_f2(&g_xn[s.z]);
            float2 v3 = ldcg_f2(&g_xn[s.w]);
            red_add_f32x2(&g_agg[d.x], v0.x, v0.y);
            red_add_f32x2(&g_agg[d.y], v1.x, v1.y);
            red_add_f32x2(&g_agg[d.z], v2.x, v2.y);
            red_add_f32x2(&g_agg[d.w], v3.x, v3.y);
        }
        if (q == 0) {
            for (long long e = quads * 4; e < E; e++) {
                float2 v = ldcg_f2(&g_xn[src[e]]);
                red_add_f32x2(&g_agg[dst[e]], v.x, v.y);
            }
        }
    } else {
        const long long* src = (const long long*)eiv;
        const long long* dst = src + E;
        if (q < quads) {
            longlong2 s0 = __ldcs((const longlong2*)(src + 4 * q));
            longlong2 s1 = __ldcs((const longlong2*)(src + 4 * q) + 1);
            longlong2 d0 = __ldcs((const longlong2*)(dst + 4 * q));
            longlong2 d1 = __ldcs((const longlong2*)(dst + 4 * q) + 1);
            float2 v0 = ldcg_f2(&g_xn[(int)s0.x]);
            float2 v1 = ldcg_f2(&g_xn[(int)s0.y]);
            float2 v2 = ldcg_f2(&g_xn[(int)s1.x]);
            float2 v3 = ldcg_f2(&g_xn[(int)s1.y]);
            red_add_f32x2(&g_agg[(int)d0.x], v0.x, v0.y);
            red_add_f32x2(&g_agg[(int)d0.y], v1.x, v1.y);
            red_add_f32x2(&g_agg[(int)d1.x], v2.x, v2.y);
            red_add_f32x2(&g_agg[(int)d1.y], v3.x, v3.y);
        }
        if (q == 0) {
            for (long long e = quads * 4; e < E; e++) {
                float2 v = ldcg_f2(&g_xn[(int)src[e]]);
                red_add_f32x2(&g_agg[(int)dst[e]], v.x, v.y);
            }
        }
    }
    PDL_TRIGGER();
}

// ---------------------------------------------------------------------------
// Kernel 3: mid-iteration: y = relu(agg @ W); renormalize; zero g_agg.
// ---------------------------------------------------------------------------
__global__ void k_mid(const float* __restrict__ W, int Npairs) {
    int i = blockIdx.x * blockDim.x + threadIdx.x;
    PDL_WAIT();
    if (i < Npairs) {
        float w00 = W[0], w01 = W[1], w10 = W[2], w11 = W[3];
        float4 a = ((const float4*)g_agg)[i];
        float y0 = fmaxf(fmaf(a.y, w10, a.x * w00), 0.0f);
        float y1 = fmaxf(fmaf(a.y, w11, a.x * w01), 0.0f);
        float y2 = fmaxf(fmaf(a.w, w10, a.z * w00), 0.0f);
        float y3 = fmaxf(fmaf(a.w, w11, a.z * w01), 0.0f);
        float inv0 = 1.0f / (sqrtf(y0 * y0 + y1 * y1) + EPSF);
        float inv1 = 1.0f / (sqrtf(y2 * y2 + y3 * y3) + EPSF);
        ((float4*)g_xn)[i] = make_float4(y0 * inv0, y1 * inv0, y2 * inv1, y3 * inv1);
        ((float4*)g_agg)[i] = make_float4(0.f, 0.f, 0.f, 0.f);
    }
    PDL_TRIGGER();
}

// ---------------------------------------------------------------------------
// Kernel 4: final: y = relu(agg @ W); out = sigmoid(y . final_weight).
// ---------------------------------------------------------------------------
__global__ void k_final(const float* __restrict__ W,
                        const float* __restrict__ fw,
                        float2* __restrict__ out, int Npairs) {
    int i = blockIdx.x * blockDim.x + threadIdx.x;
    PDL_WAIT();
    if (i < Npairs) {
        float w00 = W[0], w01 = W[1], w10 = W[2], w11 = W[3];
        float f0 = fw[0], f1 = fw[1];
        float4 a = ((const float4*)g_agg)[i];
        float y0 = fmaxf(fmaf(a.y, w10, a.x * w00), 0.0f);
        float y1 = fmaxf(fmaf(a.y, w11, a.x * w01), 0.0f);
        float y2 = fmaxf(fmaf(a.w, w10, a.z * w00), 0.0f);
        float y3 = fmaxf(fmaf(a.w, w11, a.z * w01), 0.0f);
        float s0 = fmaf(y1, f1, y0 * f0);
        float s1 = fmaf(y3, f1, y2 * f0);
        out[i] = make_float2(1.0f / (1.0f + expf(-s0)),
                             1.0f / (1.0f + expf(-s1)));
    }
    PDL_TRIGGER();
}

// ---------------------------------------------------------------------------
// Launch: init(+detect) -> scatter -> mid -> scatter -> final, all with the
// ProgrammaticStreamSerialization attribute so successive kernels overlap
// prologue/epilogue. Graph-capturable (PDL capture -> programmatic graph
// edges), allocation-free, no syncs.
// ---------------------------------------------------------------------------
extern "C" void kernel_launch(void* const* d_in, const int* in_sizes, int n_in,
                              void* d_out, int out_size) {
    const float* x  = (const float*)d_in[0];
    const void*  ei = (const void*)d_in[1];
    const float* W  = (const float*)d_in[2];
    const float* fw = (const float*)d_in[3];
    float2* out = (float2*)d_out;

    int N = in_sizes[0] / 2;          // N is even (1,000,000)
    int Npairs = N / 2;
    long long E = (long long)in_sizes[1] / 2;
    long long quads = E >> 2;

    const int TB = 256;
    int nb_pairs = (Npairs + TB - 1) / TB;
    int nb_scatter = (int)((quads + TB - 1) / TB);   // one quad per thread

    cudaLaunchAttribute attr[1];
    attr[0].id = cudaLaunchAttributeProgrammaticStreamSerialization;
    attr[0].val.programmaticStreamSerializationAllowed = 1;

    cudaLaunchConfig_t cfg = {};
    cfg.blockDim = dim3(TB, 1, 1);
    cfg.dynamicSmemBytes = 0;
    cfg.stream = 0;
    cfg.attrs = attr;
    cfg.numAttrs = 1;

    cfg.gridDim = dim3(nb_pairs, 1, 1);
    cudaLaunchKernelEx(&cfg, k_init, (const float4*)x, Npairs, N,
                       (const long long*)ei, E);

    cfg.gridDim = dim3(nb_scatter, 1, 1);
    cudaLaunchKernelEx(&cfg, k_scatter, (const void*)ei, E);

    cfg.gridDim = dim3(nb_pairs, 1, 1);
    cudaLaunchKernelEx(&cfg, k_mid, W, Npairs);

    cfg.gridDim = dim3(nb_scatter, 1, 1);
    cudaLaunchKernelEx(&cfg, k_scatter, (const void*)ei, E);

    cfg.gridDim = dim3(nb_pairs, 1, 1);
    cudaLaunchKernelEx(&cfg, k_final, W, fw, out, Npairs);

    (void)n_in; (void)out_size;
}

// round 10
// speedup vs baseline: 1.0430x; 1.0017x over previous
#include <cuda_runtime.h>
#include <math.h>

// ---------------------------------------------------------------------------
// Scratch: node state and aggregation buffer. N = 1,000,000 fits in 1<<20.
// ---------------------------------------------------------------------------
#define MAXN (1 << 20)
__device__ float2 g_xn[MAXN];
__device__ float2 g_agg[MAXN];
__device__ int    g_idx64;   // 1 if edge_index is int64, 0 if int32

#define EPSF 1e-15f

// PDL (programmatic dependent launch) primitives, sm_90+.
// wait: block until predecessor grid's memory is visible (correctness).
// launch_dependents: allow dependent grid to start its pre-wait prologue
// (pure performance knob; safe to issue as early as possible).
#define PDL_WAIT()    asm volatile("griddepcontrol.wait;" ::: "memory")
#define PDL_TRIGGER() asm volatile("griddepcontrol.launch_dependents;" ::: "memory")

__device__ __forceinline__ void red_add_f32x2(float2* p, float vx, float vy) {
    asm volatile("red.global.add.v2.f32 [%0], {%1, %2};"
                 :: "l"(p), "f"(vx), "f"(vy)
                 : "memory");
}

// L2-only 8-byte gather (random access; skip the L1 stage).
__device__ __forceinline__ float2 ldcg_f2(const float2* p) {
    float2 r;
    asm volatile("ld.global.cg.v2.f32 {%0, %1}, [%2];"
                 : "=f"(r.x), "=f"(r.y) : "l"(p));
    return r;
}

// ---------------------------------------------------------------------------
// Kernel 1: normalize x into g_xn (2 nodes/thread via float4), zero g_agg.
// Block 0 also detects the index dtype. Trigger FIRST: scatter-1's prologue
// (index prefetch) is independent of everything k_init writes.
// ---------------------------------------------------------------------------
__global__ void k_init(const float4* __restrict__ x, int Npairs, int N,
                       const long long* __restrict__ ei, long long n_words) {
    PDL_TRIGGER();
    int i = blockIdx.x * blockDim.x + threadIdx.x;
    if (i < Npairs) {
        float4 v = x[i];   // two nodes: (v.x,v.y) and (v.z,v.w)
        float inv0 = 1.0f / (sqrtf(v.x * v.x + v.y * v.y) + EPSF);
        float inv1 = 1.0f / (sqrtf(v.z * v.z + v.w * v.w) + EPSF);
        ((float4*)g_xn)[i] = make_float4(v.x * inv0, v.y * inv0,
                                         v.z * inv1, v.w * inv1);
        ((float4*)g_agg)[i] = make_float4(0.f, 0.f, 0.f, 0.f);
    }
    if (blockIdx.x == 0) {
        __shared__ int bad;
        if (threadIdx.x == 0) bad = 0;
        __syncthreads();
        long long lim = n_words < 2048 ? n_words : 2048;
        int local_bad = 0;
        for (long long w = threadIdx.x; w < lim; w += blockDim.x) {
            long long v = ei[w];
            if (v < 0 || v >= (long long)N) local_bad = 1;
        }
        if (local_bad) bad = 1;
        __syncthreads();
        if (threadIdx.x == 0) g_idx64 = bad ? 0 : 1;
    }
}

// ---------------------------------------------------------------------------
// Kernel 2: edge scatter: g_agg[dst[e]] += g_xn[src[e]].
// Measured-best shape (232.3us, occ 81%, regs 32): one quad per thread,
// __ldcs index loads, L2-only gathers, 4 gathers batched before 4 reds.
// Trigger FIRST (dependent elementwise kernels park in their PDL_WAIT).
// Prologue prefetches the index quad before the wait (input data, never
// written by any of our kernels); g_idx64/g_xn/g_agg only after PDL_WAIT.
// ---------------------------------------------------------------------------
__global__ void __launch_bounds__(256) k_scatter(const void* __restrict__ eiv, long long E) {
    PDL_TRIGGER();
    long long q = (long long)blockIdx.x * blockDim.x + threadIdx.x;
    long long quads = E >> 2;

    // Prefetch assuming int32 layout (the actual case). For int64 data these
    // are still in-bounds reads of the same buffer; values are discarded.
    int4 s = make_int4(0, 0, 0, 0), d = make_int4(0, 0, 0, 0);
    if (q < quads) {
        const int* src32 = (const int*)eiv;
        s = __ldcs((const int4*)(src32 + 4 * q));
        d = __ldcs((const int4*)(src32 + E + 4 * q));
    }

    PDL_WAIT();

    if (g_idx64 == 0) {
        const int* src = (const int*)eiv;
        const int* dst = src + E;
        if (q < quads) {
            float2 v0 = ldcg_f2(&g_xn[s.x]);
            float2 v1 = ldcg_f2(&g_xn[s.y]);
            float2 v2 = ldcg_f2(&g_xn[s.z]);
            float2 v3 = ldcg_f2(&g_xn[s.w]);
            red_add_f32x2(&g_agg[d.x], v0.x, v0.y);
            red_add_f32x2(&g_agg[d.y], v1.x, v1.y);
            red_add_f32x2(&g_agg[d.z], v2.x, v2.y);
            red_add_f32x2(&g_agg[d.w], v3.x, v3.y);
        }
        if (q == 0) {
            for (long long e = quads * 4; e < E; e++) {
                float2 v = ldcg_f2(&g_xn[src[e]]);
                red_add_f32x2(&g_agg[dst[e]], v.x, v.y);
            }
        }
    } else {
        const long long* src = (const long long*)eiv;
        const long long* dst = src + E;
        if (q < quads) {
            longlong2 s0 = __ldcs((const longlong2*)(src + 4 * q));
            longlong2 s1 = __ldcs((const longlong2*)(src + 4 * q) + 1);
            longlong2 d0 = __ldcs((const longlong2*)(dst + 4 * q));
            longlong2 d1 = __ldcs((const longlong2*)(dst + 4 * q) + 1);
            float2 v0 = ldcg_f2(&g_xn[(int)s0.x]);
            float2 v1 = ldcg_f2(&g_xn[(int)s0.y]);
            float2 v2 = ldcg_f2(&g_xn[(int)s1.x]);
            float2 v3 = ldcg_f2(&g_xn[(int)s1.y]);
            red_add_f32x2(&g_agg[(int)d0.x], v0.x, v0.y);
            red_add_f32x2(&g_agg[(int)d0.y], v1.x, v1.y);
            red_add_f32x2(&g_agg[(int)d1.x], v2.x, v2.y);
            red_add_f32x2(&g_agg[(int)d1.y], v3.x, v3.y);
        }
        if (q == 0) {
            for (long long e = quads * 4; e < E; e++) {
                float2 v = ldcg_f2(&g_xn[(int)src[e]]);
                red_add_f32x2(&g_agg[(int)dst[e]], v.x, v.y);
            }
        }
    }
}

// ---------------------------------------------------------------------------
// Kernel 3: mid-iteration: y = relu(agg @ W); renormalize; zero g_agg.
// Trigger FIRST (scatter-2's prologue only reads edge indices, which k_mid
// never writes). Prologue pre-loads W (input, written by nobody).
// ---------------------------------------------------------------------------
__global__ void k_mid(const float* __restrict__ W, int Npairs) {
    PDL_TRIGGER();
    int i = blockIdx.x * blockDim.x + threadIdx.x;
    float w00 = W[0], w01 = W[1], w10 = W[2], w11 = W[3];
    PDL_WAIT();
    if (i < Npairs) {
        float4 a = ((const float4*)g_agg)[i];
        float y0 = fmaxf(fmaf(a.y, w10, a.x * w00), 0.0f);
        float y1 = fmaxf(fmaf(a.y, w11, a.x * w01), 0.0f);
        float y2 = fmaxf(fmaf(a.w, w10, a.z * w00), 0.0f);
        float y3 = fmaxf(fmaf(a.w, w11, a.z * w01), 0.0f);
        float inv0 = 1.0f / (sqrtf(y0 * y0 + y1 * y1) + EPSF);
        float inv1 = 1.0f / (sqrtf(y2 * y2 + y3 * y3) + EPSF);
        ((float4*)g_xn)[i] = make_float4(y0 * inv0, y1 * inv0, y2 * inv1, y3 * inv1);
        ((float4*)g_agg)[i] = make_float4(0.f, 0.f, 0.f, 0.f);
    }
}

// ---------------------------------------------------------------------------
// Kernel 4: final: y = relu(agg @ W); out = sigmoid(y . final_weight).
// Prologue pre-loads the weight scalars before the wait.
// ---------------------------------------------------------------------------
__global__ void k_final(const float* __restrict__ W,
                        const float* __restrict__ fw,
                        float2* __restrict__ out, int Npairs) {
    int i = blockIdx.x * blockDim.x + threadIdx.x;
    float w00 = W[0], w01 = W[1], w10 = W[2], w11 = W[3];
    float f0 = fw[0], f1 = fw[1];
    PDL_WAIT();
    if (i < Npairs) {
        float4 a = ((const float4*)g_agg)[i];
        float y0 = fmaxf(fmaf(a.y, w10, a.x * w00), 0.0f);
        float y1 = fmaxf(fmaf(a.y, w11, a.x * w01), 0.0f);
        float y2 = fmaxf(fmaf(a.w, w10, a.z * w00), 0.0f);
        float y3 = fmaxf(fmaf(a.w, w11, a.z * w01), 0.0f);
        float s0 = fmaf(y1, f1, y0 * f0);
        float s1 = fmaf(y3, f1, y2 * f0);
        out[i] = make_float2(1.0f / (1.0f + expf(-s0)),
                             1.0f / (1.0f + expf(-s1)));
    }
}

// ---------------------------------------------------------------------------
// Launch: init(+detect) -> scatter -> mid -> scatter -> final with
// programmatic stream serialization (PDL). Graph-capturable, allocation-free.
// ---------------------------------------------------------------------------
extern "C" void kernel_launch(void* const* d_in, const int* in_sizes, int n_in,
                              void* d_out, int out_size) {
    const float* x  = (const float*)d_in[0];
    const void*  ei = (const void*)d_in[1];
    const float* W  = (const float*)d_in[2];
    const float* fw = (const float*)d_in[3];
    float2* out = (float2*)d_out;

    int N = in_sizes[0] / 2;          // N is even (1,000,000)
    int Npairs = N / 2;
    long long E = (long long)in_sizes[1] / 2;
    long long quads = E >> 2;

    const int TB = 256;
    int nb_pairs = (Npairs + TB - 1) / TB;
    int nb_scatter = (int)((quads + TB - 1) / TB);   // one quad per thread

    cudaLaunchAttribute attr[1];
    attr[0].id = cudaLaunchAttributeProgrammaticStreamSerialization;
    attr[0].val.programmaticStreamSerializationAllowed = 1;

    cudaLaunchConfig_t cfg = {};
    cfg.blockDim = dim3(TB, 1, 1);
    cfg.dynamicSmemBytes = 0;
    cfg.stream = 0;
    cfg.attrs = attr;
    cfg.numAttrs = 1;

    cfg.gridDim = dim3(nb_pairs, 1, 1);
    cudaLaunchKernelEx(&cfg, k_init, (const float4*)x, Npairs, N,
                       (const long long*)ei, E);

    cfg.gridDim = dim3(nb_scatter, 1, 1);
    cudaLaunchKernelEx(&cfg, k_scatter, (const void*)ei, E);

    cfg.gridDim = dim3(nb_pairs, 1, 1);
    cudaLaunchKernelEx(&cfg, k_mid, W, Npairs);

    cfg.gridDim = dim3(nb_scatter, 1, 1);
    cudaLaunchKernelEx(&cfg, k_scatter, (const void*)ei, E);

    cfg.gridDim = dim3(nb_pairs, 1, 1);
    cudaLaunchKernelEx(&cfg, k_final, W, fw, out, Npairs);

    (void)n_in; (void)out_size;
}

// round 11
// speedup vs baseline: 1.1216x; 1.0753x over previous
#include <cuda_runtime.h>
#include <math.h>

// ---------------------------------------------------------------------------
// Scratch. N = 1,000,000 fits in 1<<20.
// ---------------------------------------------------------------------------
#define MAXN (1 << 20)
__device__ float2        g_xn[MAXN];          // node state
__device__ float2        g_agg[MAXN];         // float aggregation (pass1 + fallback)
__device__ unsigned int  g_cntA[MAXN];        // pass2 clean: count of (1,0) sources
__device__ unsigned int  g_cntB[MAXN];        // pass2 clean: count of (0,1) sources
__device__ unsigned char g_clsp[MAXN / 4];    // 2-bit class per node, packed 4/byte
__device__ int           g_idx64;             // 1 if edge_index is int64
__device__ int           g_notclean;          // 1 if any node state is not one-sided

#define EPSF 1e-15f

#define PDL_WAIT()    asm volatile("griddepcontrol.wait;" ::: "memory")
#define PDL_TRIGGER() asm volatile("griddepcontrol.launch_dependents;" ::: "memory")

__device__ __forceinline__ void red_add_f32x2(float2* p, float vx, float vy) {
    asm volatile("red.global.add.v2.f32 [%0], {%1, %2};"
                 :: "l"(p), "f"(vx), "f"(vy)
                 : "memory");
}
__device__ __forceinline__ void red_add_u32(unsigned int* p, unsigned int v) {
    asm volatile("red.global.add.u32 [%0], %1;"
                 :: "l"(p), "r"(v)
                 : "memory");
}
__device__ __forceinline__ float2 ldcg_f2(const float2* p) {
    float2 r;
    asm volatile("ld.global.cg.v2.f32 {%0, %1}, [%2];"
                 : "=f"(r.x), "=f"(r.y) : "l"(p));
    return r;
}

// ---------------------------------------------------------------------------
// Kernel 1: normalize x into g_xn (2 nodes/thread), zero g_agg, detect dtype.
// ---------------------------------------------------------------------------
__global__ void k_init(const float4* __restrict__ x, int Npairs, int N,
                       const long long* __restrict__ ei, long long n_words) {
    PDL_TRIGGER();
    int i = blockIdx.x * blockDim.x + threadIdx.x;
    if (i < Npairs) {
        float4 v = x[i];
        float inv0 = 1.0f / (sqrtf(v.x * v.x + v.y * v.y) + EPSF);
        float inv1 = 1.0f / (sqrtf(v.z * v.z + v.w * v.w) + EPSF);
        ((float4*)g_xn)[i] = make_float4(v.x * inv0, v.y * inv0,
                                         v.z * inv1, v.w * inv1);
        ((float4*)g_agg)[i] = make_float4(0.f, 0.f, 0.f, 0.f);
    }
    if (blockIdx.x == 0) {
        if (threadIdx.x == 0) g_notclean = 0;
        __shared__ int bad;
        if (threadIdx.x == 0) bad = 0;
        __syncthreads();
        long long lim = n_words < 2048 ? n_words : 2048;
        int local_bad = 0;
        for (long long w = threadIdx.x; w < lim; w += blockDim.x) {
            long long v = ei[w];
            if (v < 0 || v >= (long long)N) local_bad = 1;
        }
        if (local_bad) bad = 1;
        __syncthreads();
        if (threadIdx.x == 0) g_idx64 = bad ? 0 : 1;
    }
}

// ---------------------------------------------------------------------------
// Kernel 2: pass-1 float scatter (measured best shape: one quad per thread).
// ---------------------------------------------------------------------------
__global__ void __launch_bounds__(256) k_scatter(const void* __restrict__ eiv, long long E) {
    PDL_TRIGGER();
    long long q = (long long)blockIdx.x * blockDim.x + threadIdx.x;
    long long quads = E >> 2;

    int4 s = make_int4(0, 0, 0, 0), d = make_int4(0, 0, 0, 0);
    if (q < quads) {
        const int* src32 = (const int*)eiv;
        s = __ldcs((const int4*)(src32 + 4 * q));
        d = __ldcs((const int4*)(src32 + E + 4 * q));
    }

    PDL_WAIT();

    if (g_idx64 == 0) {
        const int* src = (const int*)eiv;
        const int* dst = src + E;
        if (q < quads) {
            float2 v0 = ldcg_f2(&g_xn[s.x]);
            float2 v1 = ldcg_f2(&g_xn[s.y]);
            float2 v2 = ldcg_f2(&g_xn[s.z]);
            float2 v3 = ldcg_f2(&g_xn[s.w]);
            red_add_f32x2(&g_agg[d.x], v0.x, v0.y);
            red_add_f32x2(&g_agg[d.y], v1.x, v1.y);
            red_add_f32x2(&g_agg[d.z], v2.x, v2.y);
            red_add_f32x2(&g_agg[d.w], v3.x, v3.y);
        }
        if (q == 0) {
            for (long long e = quads * 4; e < E; e++) {
                float2 v = ldcg_f2(&g_xn[src[e]]);
                red_add_f32x2(&g_agg[dst[e]], v.x, v.y);
            }
        }
    } else {
        const long long* src = (const long long*)eiv;
        const long long* dst = src + E;
        if (q < quads) {
            longlong2 s0 = __ldcs((const longlong2*)(src + 4 * q));
            longlong2 s1 = __ldcs((const longlong2*)(src + 4 * q) + 1);
            longlong2 d0 = __ldcs((const longlong2*)(dst + 4 * q));
            longlong2 d1 = __ldcs((const longlong2*)(dst + 4 * q) + 1);
            float2 v0 = ldcg_f2(&g_xn[(int)s0.x]);
            float2 v1 = ldcg_f2(&g_xn[(int)s0.y]);
            float2 v2 = ldcg_f2(&g_xn[(int)s1.x]);
            float2 v3 = ldcg_f2(&g_xn[(int)s1.y]);
            red_add_f32x2(&g_agg[(int)d0.x], v0.x, v0.y);
            red_add_f32x2(&g_agg[(int)d0.y], v1.x, v1.y);
            red_add_f32x2(&g_agg[(int)d1.x], v2.x, v2.y);
            red_add_f32x2(&g_agg[(int)d1.y], v3.x, v3.y);
        }
        if (q == 0) {
            for (long long e = quads * 4; e < E; e++) {
                float2 v = ldcg_f2(&g_xn[(int)src[e]]);
                red_add_f32x2(&g_agg[(int)dst[e]], v.x, v.y);
            }
        }
    }
}

// ---------------------------------------------------------------------------
// Kernel 3: mid-iteration: y = relu(agg @ W). 4 nodes per thread.
// Classify each node: post-relu state (t,0)->class0 (xn=(1,0) exact),
// (0,t)->class1 (xn=(0,1) exact), (0,0)->class2, both>0 -> class3 (general
// normalize, set g_notclean). Pack 4 classes into one byte. Zero the count
// arrays and g_agg for pass 2.
// ---------------------------------------------------------------------------
__global__ void k_mid(const float* __restrict__ W, int Nquads) {
    PDL_TRIGGER();
    int i = blockIdx.x * blockDim.x + threadIdx.x;
    float w00 = W[0], w01 = W[1], w10 = W[2], w11 = W[3];
    PDL_WAIT();
    if (i >= Nquads) return;

    float4 a01 = ((const float4*)g_agg)[2 * i];
    float4 a23 = ((const float4*)g_agg)[2 * i + 1];
    float ax[4] = {a01.x, a01.z, a23.x, a23.z};
    float ay[4] = {a01.y, a01.w, a23.y, a23.w};
    float xo[8];
    unsigned int clsbyte = 0;
    bool dirty = false;

    #pragma unroll
    for (int j = 0; j < 4; j++) {
        float y0 = fmaf(ay[j], w10, ax[j] * w00);
        float y1 = fmaf(ay[j], w11, ax[j] * w01);
        float r0 = fmaxf(y0, 0.0f);
        float r1 = fmaxf(y1, 0.0f);
        unsigned int c;
        float x0, x1;
        if (r1 == 0.0f) {
            if (r0 > 0.0f) { c = 0u; x0 = 1.0f; x1 = 0.0f; }
            else           { c = 2u; x0 = 0.0f; x1 = 0.0f; }
        } else if (r0 == 0.0f) {
            c = 1u; x0 = 0.0f; x1 = 1.0f;
        } else {
            c = 3u; dirty = true;
            float inv = 1.0f / (sqrtf(r0 * r0 + r1 * r1) + EPSF);
            x0 = r0 * inv; x1 = r1 * inv;
        }
        clsbyte |= c << (2 * j);
        xo[2 * j] = x0; xo[2 * j + 1] = x1;
    }

    ((float4*)g_xn)[2 * i]     = make_float4(xo[0], xo[1], xo[2], xo[3]);
    ((float4*)g_xn)[2 * i + 1] = make_float4(xo[4], xo[5], xo[6], xo[7]);
    ((float4*)g_agg)[2 * i]     = make_float4(0.f, 0.f, 0.f, 0.f);
    ((float4*)g_agg)[2 * i + 1] = make_float4(0.f, 0.f, 0.f, 0.f);
    ((uint4*)g_cntA)[i] = make_uint4(0u, 0u, 0u, 0u);
    ((uint4*)g_cntB)[i] = make_uint4(0u, 0u, 0u, 0u);
    g_clsp[i] = (unsigned char)clsbyte;
    if (dirty) g_notclean = 1;
}

// ---------------------------------------------------------------------------
// Kernel 2b: pass-2 scatter. Clean mode: gather a 2-bit class from the 256KB
// packed array (L1-resident -> no L2 gather traffic) and count into cntA/cntB
// with 4B reds (class 2 skips the red). Fallback: float path.
// ---------------------------------------------------------------------------
__device__ __forceinline__ unsigned int cls_of(int node) {
    unsigned int b = (unsigned int)g_clsp[node >> 2];
    return (b >> ((node & 3) << 1)) & 3u;
}
__device__ __forceinline__ void count_edge(unsigned int c, int dnode) {
    if (c == 0u)      red_add_u32(&g_cntA[dnode], 1u);
    else if (c == 1u) red_add_u32(&g_cntB[dnode], 1u);
}

__global__ void __launch_bounds__(256) k_scatter2(const void* __restrict__ eiv, long long E) {
    PDL_TRIGGER();
    long long q = (long long)blockIdx.x * blockDim.x + threadIdx.x;
    long long quads = E >> 2;

    int4 s = make_int4(0, 0, 0, 0), d = make_int4(0, 0, 0, 0);
    if (q < quads) {
        const int* src32 = (const int*)eiv;
        s = __ldcs((const int4*)(src32 + 4 * q));
        d = __ldcs((const int4*)(src32 + E + 4 * q));
    }

    PDL_WAIT();

    if (g_idx64 == 0 && g_notclean == 0) {
        // Clean class-count path.
        const int* src = (const int*)eiv;
        const int* dst = src + E;
        if (q < quads) {
            unsigned int c0 = cls_of(s.x);
            unsigned int c1 = cls_of(s.y);
            unsigned int c2 = cls_of(s.z);
            unsigned int c3 = cls_of(s.w);
            count_edge(c0, d.x);
            count_edge(c1, d.y);
            count_edge(c2, d.z);
            count_edge(c3, d.w);
        }
        if (q == 0) {
            for (long long e = quads * 4; e < E; e++)
                count_edge(cls_of(src[e]), dst[e]);
        }
    } else if (g_idx64 == 0) {
        const int* src = (const int*)eiv;
        const int* dst = src + E;
        if (q < quads) {
            float2 v0 = ldcg_f2(&g_xn[s.x]);
            float2 v1 = ldcg_f2(&g_xn[s.y]);
            float2 v2 = ldcg_f2(&g_xn[s.z]);
            float2 v3 = ldcg_f2(&g_xn[s.w]);
            red_add_f32x2(&g_agg[d.x], v0.x, v0.y);
            red_add_f32x2(&g_agg[d.y], v1.x, v1.y);
            red_add_f32x2(&g_agg[d.z], v2.x, v2.y);
            red_add_f32x2(&g_agg[d.w], v3.x, v3.y);
        }
        if (q == 0) {
            for (long long e = quads * 4; e < E; e++) {
                float2 v = ldcg_f2(&g_xn[src[e]]);
                red_add_f32x2(&g_agg[dst[e]], v.x, v.y);
            }
        }
    } else {
        const long long* src = (const long long*)eiv;
        const long long* dst = src + E;
        if (q < quads) {
            longlong2 s0 = __ldcs((const longlong2*)(src + 4 * q));
            longlong2 s1 = __ldcs((const longlong2*)(src + 4 * q) + 1);
            longlong2 d0 = __ldcs((const longlong2*)(dst + 4 * q));
            longlong2 d1 = __ldcs((const longlong2*)(dst + 4 * q) + 1);
            float2 v0 = ldcg_f2(&g_xn[(int)s0.x]);
            float2 v1 = ldcg_f2(&g_xn[(int)s0.y]);
            float2 v2 = ldcg_f2(&g_xn[(int)s1.x]);
            float2 v3 = ldcg_f2(&g_xn[(int)s1.y]);
            red_add_f32x2(&g_agg[(int)d0.x], v0.x, v0.y);
            red_add_f32x2(&g_agg[(int)d0.y], v1.x, v1.y);
            red_add_f32x2(&g_agg[(int)d1.x], v2.x, v2.y);
            red_add_f32x2(&g_agg[(int)d1.y], v3.x, v3.y);
        }
        if (q == 0) {
            for (long long e = quads * 4; e < E; e++) {
                float2 v = ldcg_f2(&g_xn[(int)src[e]]);
                red_add_f32x2(&g_agg[(int)dst[e]], v.x, v.y);
            }
        }
    }
}

// ---------------------------------------------------------------------------
// Kernel 4: final. Clean mode: agg = (cntA, cntB) (exact integers, matching
// the reference's exact sums of 1.0f). Fallback: read g_agg.
// ---------------------------------------------------------------------------
__global__ void k_final(const float* __restrict__ W,
                        const float* __restrict__ fw,
                        float2* __restrict__ out, int Npairs) {
    int i = blockIdx.x * blockDim.x + threadIdx.x;
    float w00 = W[0], w01 = W[1], w10 = W[2], w11 = W[3];
    float f0 = fw[0], f1 = fw[1];
    PDL_WAIT();
    if (i >= Npairs) return;

    float4 a;
    if (g_notclean == 0) {
        uint2 cA = ((const uint2*)g_cntA)[i];
        uint2 cB = ((const uint2*)g_cntB)[i];
        a = make_float4((float)cA.x, (float)cB.x, (float)cA.y, (float)cB.y);
    } else {
        a = ((const float4*)g_agg)[i];
    }
    float y0 = fmaxf(fmaf(a.y, w10, a.x * w00), 0.0f);
    float y1 = fmaxf(fmaf(a.y, w11, a.x * w01), 0.0f);
    float y2 = fmaxf(fmaf(a.w, w10, a.z * w00), 0.0f);
    float y3 = fmaxf(fmaf(a.w, w11, a.z * w01), 0.0f);
    float s0 = fmaf(y1, f1, y0 * f0);
    float s1 = fmaf(y3, f1, y2 * f0);
    out[i] = make_float2(1.0f / (1.0f + expf(-s0)),
                         1.0f / (1.0f + expf(-s1)));
}

// ---------------------------------------------------------------------------
// Launch: init -> scatter -> mid -> scatter2 -> final with PDL.
// ---------------------------------------------------------------------------
extern "C" void kernel_launch(void* const* d_in, const int* in_sizes, int n_in,
                              void* d_out, int out_size) {
    const float* x  = (const float*)d_in[0];
    const void*  ei = (const void*)d_in[1];
    const float* W  = (const float*)d_in[2];
    const float* fw = (const float*)d_in[3];
    float2* out = (float2*)d_out;

    int N = in_sizes[0] / 2;          // 1,000,000 (divisible by 4)
    int Npairs = N / 2;
    int Nquads = N / 4;
    long long E = (long long)in_sizes[1] / 2;
    long long equads = E >> 2;

    const int TB = 256;
    int nb_pairs = (Npairs + TB - 1) / TB;
    int nb_quads = (Nquads + TB - 1) / TB;
    int nb_scatter = (int)((equads + TB - 1) / TB);

    cudaLaunchAttribute attr[1];
    attr[0].id = cudaLaunchAttributeProgrammaticStreamSerialization;
    attr[0].val.programmaticStreamSerializationAllowed = 1;

    cudaLaunchConfig_t cfg = {};
    cfg.blockDim = dim3(TB, 1, 1);
    cfg.dynamicSmemBytes = 0;
    cfg.stream = 0;
    cfg.attrs = attr;
    cfg.numAttrs = 1;

    cfg.gridDim = dim3(nb_pairs, 1, 1);
    cudaLaunchKernelEx(&cfg, k_init, (const float4*)x, Npairs, N,
                       (const long long*)ei, E);

    cfg.gridDim = dim3(nb_scatter, 1, 1);
    cudaLaunchKernelEx(&cfg, k_scatter, (const void*)ei, E);

    cfg.gridDim = dim3(nb_quads, 1, 1);
    cudaLaunchKernelEx(&cfg, k_mid, W, Nquads);

    cfg.gridDim = dim3(nb_scatter, 1, 1);
    cudaLaunchKernelEx(&cfg, k_scatter2, (const void*)ei, E);

    cfg.gridDim = dim3(nb_pairs, 1, 1);
    cudaLaunchKernelEx(&cfg, k_final, W, fw, out, Npairs);

    (void)n_in; (void)out_size;
}

// round 12
// speedup vs baseline: 1.6758x; 1.4942x over previous
#include <cuda_runtime.h>
#include <math.h>

// ---------------------------------------------------------------------------
// Scratch. N = 1,000,000 fits in 1<<20.
// ---------------------------------------------------------------------------
#define MAXN (1 << 20)
__device__ float4        g_aggd[MAXN];        // pass1: (sum_x, sum_y, degree, 0)
__device__ float2        g_xn[MAXN];          // node state
__device__ float2        g_agg[MAXN];         // pass2 float fallback accumulator
__device__ unsigned int  g_cntA[MAXN];        // pass2: count of class-0 ((1,0)) sources
__device__ unsigned int  g_cntB[MAXN];        // pass2: count of class-2 ((0,0)) sources
__device__ unsigned char g_clsp[MAXN / 4];    // 2-bit class per node, packed 4/byte
__device__ int           g_idx64;             // 1 if edge_index is int64
__device__ int           g_notclean;          // 1 if any node is class 3 (general)
__device__ int           g_anyAB;             // 1 if any node is class 0 or 2

#define EPSF 1e-15f

#define PDL_WAIT()    asm volatile("griddepcontrol.wait;" ::: "memory")
#define PDL_TRIGGER() asm volatile("griddepcontrol.launch_dependents;" ::: "memory")

__device__ __forceinline__ void red_add_f32x4(float4* p, float a, float b,
                                              float c, float d) {
    asm volatile("red.global.add.v4.f32 [%0], {%1, %2, %3, %4};"
                 :: "l"(p), "f"(a), "f"(b), "f"(c), "f"(d)
                 : "memory");
}
__device__ __forceinline__ void red_add_f32x2(float2* p, float vx, float vy) {
    asm volatile("red.global.add.v2.f32 [%0], {%1, %2};"
                 :: "l"(p), "f"(vx), "f"(vy)
                 : "memory");
}
__device__ __forceinline__ void red_add_u32(unsigned int* p, unsigned int v) {
    asm volatile("red.global.add.u32 [%0], %1;"
                 :: "l"(p), "r"(v)
                 : "memory");
}
__device__ __forceinline__ float2 ldcg_f2(const float2* p) {
    float2 r;
    asm volatile("ld.global.cg.v2.f32 {%0, %1}, [%2];"
                 : "=f"(r.x), "=f"(r.y) : "l"(p));
    return r;
}

// ---------------------------------------------------------------------------
// Kernel 1: normalize x into g_xn (2 nodes/thread), zero g_aggd, detect dtype.
// ---------------------------------------------------------------------------
__global__ void k_init(const float4* __restrict__ x, int Npairs, int N,
                       const long long* __restrict__ ei, long long n_words) {
    PDL_TRIGGER();
    int i = blockIdx.x * blockDim.x + threadIdx.x;
    if (i < Npairs) {
        float4 v = x[i];
        float inv0 = 1.0f / (sqrtf(v.x * v.x + v.y * v.y) + EPSF);
        float inv1 = 1.0f / (sqrtf(v.z * v.z + v.w * v.w) + EPSF);
        ((float4*)g_xn)[i] = make_float4(v.x * inv0, v.y * inv0,
                                         v.z * inv1, v.w * inv1);
        g_aggd[2 * i]     = make_float4(0.f, 0.f, 0.f, 0.f);
        g_aggd[2 * i + 1] = make_float4(0.f, 0.f, 0.f, 0.f);
    }
    if (blockIdx.x == 0) {
        if (threadIdx.x == 0) { g_notclean = 0; g_anyAB = 0; }
        __shared__ int bad;
        if (threadIdx.x == 0) bad = 0;
        __syncthreads();
        long long lim = n_words < 2048 ? n_words : 2048;
        int local_bad = 0;
        for (long long w = threadIdx.x; w < lim; w += blockDim.x) {
            long long v = ei[w];
            if (v < 0 || v >= (long long)N) local_bad = 1;
        }
        if (local_bad) bad = 1;
        __syncthreads();
        if (threadIdx.x == 0) g_idx64 = bad ? 0 : 1;
    }
}

// ---------------------------------------------------------------------------
// Kernel 2: pass-1 scatter with fused degree count:
// g_aggd[dst] += (xn[src].x, xn[src].y, 1, 0)  via one v4 red per edge
// (same 32B sector / wavefront cost as the old v2 red).
// ---------------------------------------------------------------------------
__global__ void __launch_bounds__(256) k_scatter(const void* __restrict__ eiv, long long E) {
    PDL_TRIGGER();
    long long q = (long long)blockIdx.x * blockDim.x + threadIdx.x;
    long long quads = E >> 2;

    int4 s = make_int4(0, 0, 0, 0), d = make_int4(0, 0, 0, 0);
    if (q < quads) {
        const int* src32 = (const int*)eiv;
        s = __ldcs((const int4*)(src32 + 4 * q));
        d = __ldcs((const int4*)(src32 + E + 4 * q));
    }

    PDL_WAIT();

    if (g_idx64 == 0) {
        const int* src = (const int*)eiv;
        const int* dst = src + E;
        if (q < quads) {
            float2 v0 = ldcg_f2(&g_xn[s.x]);
            float2 v1 = ldcg_f2(&g_xn[s.y]);
            float2 v2 = ldcg_f2(&g_xn[s.z]);
            float2 v3 = ldcg_f2(&g_xn[s.w]);
            red_add_f32x4(&g_aggd[d.x], v0.x, v0.y, 1.0f, 0.0f);
            red_add_f32x4(&g_aggd[d.y], v1.x, v1.y, 1.0f, 0.0f);
            red_add_f32x4(&g_aggd[d.z], v2.x, v2.y, 1.0f, 0.0f);
            red_add_f32x4(&g_aggd[d.w], v3.x, v3.y, 1.0f, 0.0f);
        }
        if (q == 0) {
            for (long long e = quads * 4; e < E; e++) {
                float2 v = ldcg_f2(&g_xn[src[e]]);
                red_add_f32x4(&g_aggd[dst[e]], v.x, v.y, 1.0f, 0.0f);
            }
        }
    } else {
        const long long* src = (const long long*)eiv;
        const long long* dst = src + E;
        if (q < quads) {
            longlong2 s0 = __ldcs((const longlong2*)(src + 4 * q));
            longlong2 s1 = __ldcs((const longlong2*)(src + 4 * q) + 1);
            longlong2 d0 = __ldcs((const longlong2*)(dst + 4 * q));
            longlong2 d1 = __ldcs((const longlong2*)(dst + 4 * q) + 1);
            float2 v0 = ldcg_f2(&g_xn[(int)s0.x]);
            float2 v1 = ldcg_f2(&g_xn[(int)s0.y]);
            float2 v2 = ldcg_f2(&g_xn[(int)s1.x]);
            float2 v3 = ldcg_f2(&g_xn[(int)s1.y]);
            red_add_f32x4(&g_aggd[(int)d0.x], v0.x, v0.y, 1.0f, 0.0f);
            red_add_f32x4(&g_aggd[(int)d0.y], v1.x, v1.y, 1.0f, 0.0f);
            red_add_f32x4(&g_aggd[(int)d1.x], v2.x, v2.y, 1.0f, 0.0f);
            red_add_f32x4(&g_aggd[(int)d1.y], v3.x, v3.y, 1.0f, 0.0f);
        }
        if (q == 0) {
            for (long long e = quads * 4; e < E; e++) {
                float2 v = ldcg_f2(&g_xn[(int)src[e]]);
                red_add_f32x4(&g_aggd[(int)dst[e]], v.x, v.y, 1.0f, 0.0f);
            }
        }
    }
}

// ---------------------------------------------------------------------------
// Kernel 3: y = relu(agg @ W), classify 4 nodes/thread:
//   class 0: (t,0), t>1e-6  -> xn=(1,0) exact     (flags g_anyAB)
//   class 1: (0,t), t>1e-6  -> xn=(0,1) exact     (expected universal case)
//   class 2: (0,0)          -> xn=(0,0)           (flags g_anyAB)
//   class 3: anything else  -> general normalize  (flags g_notclean)
// Zero count arrays + float fallback accumulator for pass 2.
// ---------------------------------------------------------------------------
__global__ void k_mid(const float* __restrict__ W, int Nquads) {
    PDL_TRIGGER();
    int i = blockIdx.x * blockDim.x + threadIdx.x;
    float w00 = W[0], w01 = W[1], w10 = W[2], w11 = W[3];
    PDL_WAIT();
    if (i >= Nquads) return;

    float xo[8];
    unsigned int clsbyte = 0;
    bool dirty = false, anyab = false;

    #pragma unroll
    for (int j = 0; j < 4; j++) {
        float4 ad = g_aggd[4 * i + j];
        float y0 = fmaf(ad.y, w10, ad.x * w00);
        float y1 = fmaf(ad.y, w11, ad.x * w01);
        float r0 = fmaxf(y0, 0.0f);
        float r1 = fmaxf(y1, 0.0f);
        unsigned int c;
        float x0, x1;
        if (r0 == 0.0f && r1 > 1e-6f) {
            c = 1u; x0 = 0.0f; x1 = 1.0f;              // (0, t/(t+eps)) == (0,1)
        } else if (r1 == 0.0f && r0 > 1e-6f) {
            c = 0u; x0 = 1.0f; x1 = 0.0f; anyab = true;
        } else if (r0 == 0.0f && r1 == 0.0f) {
            c = 2u; x0 = 0.0f; x1 = 0.0f; anyab = true;
        } else {
            c = 3u; dirty = true;
            float inv = 1.0f / (sqrtf(r0 * r0 + r1 * r1) + EPSF);
            x0 = r0 * inv; x1 = r1 * inv;
        }
        clsbyte |= c << (2 * j);
        xo[2 * j] = x0; xo[2 * j + 1] = x1;
    }

    ((float4*)g_xn)[2 * i]     = make_float4(xo[0], xo[1], xo[2], xo[3]);
    ((float4*)g_xn)[2 * i + 1] = make_float4(xo[4], xo[5], xo[6], xo[7]);
    ((float4*)g_agg)[2 * i]     = make_float4(0.f, 0.f, 0.f, 0.f);
    ((float4*)g_agg)[2 * i + 1] = make_float4(0.f, 0.f, 0.f, 0.f);
    ((uint4*)g_cntA)[i] = make_uint4(0u, 0u, 0u, 0u);
    ((uint4*)g_cntB)[i] = make_uint4(0u, 0u, 0u, 0u);
    g_clsp[i] = (unsigned char)clsbyte;
    if (dirty) g_notclean = 1;
    if (anyab) g_anyAB = 1;
}

// ---------------------------------------------------------------------------
// Kernel 2b: pass-2 scatter, tiered.
//   all nodes class 1 (expected): agg fully determined by degree -> EXIT.
//   clean but some class 0/2: count only those rare classes per dst.
//   class-3 present: full float fallback into g_agg.
// ---------------------------------------------------------------------------
__device__ __forceinline__ unsigned int cls_of(int node) {
    unsigned int b = (unsigned int)g_clsp[node >> 2];
    return (b >> ((node & 3) << 1)) & 3u;
}
__device__ __forceinline__ void count_rare(unsigned int c, int dnode) {
    if (c == 0u)      red_add_u32(&g_cntA[dnode], 1u);
    else if (c == 2u) red_add_u32(&g_cntB[dnode], 1u);
}

__global__ void __launch_bounds__(256) k_scatter2(const void* __restrict__ eiv, long long E) {
    PDL_TRIGGER();
    PDL_WAIT();
    if (g_notclean == 0 && g_anyAB == 0) return;   // degree-only: nothing to do

    long long q = (long long)blockIdx.x * blockDim.x + threadIdx.x;
    long long quads = E >> 2;

    if (g_notclean == 0) {
        // Rare-class count path.
        if (g_idx64 == 0) {
            const int* src = (const int*)eiv;
            const int* dst = src + E;
            if (q < quads) {
                int4 s = __ldcs((const int4*)(src + 4 * q));
                int4 d = __ldcs((const int4*)(dst + 4 * q));
                count_rare(cls_of(s.x), d.x);
                count_rare(cls_of(s.y), d.y);
                count_rare(cls_of(s.z), d.z);
                count_rare(cls_of(s.w), d.w);
            }
            if (q == 0) {
                for (long long e = quads * 4; e < E; e++)
                    count_rare(cls_of(src[e]), dst[e]);
            }
        } else {
            const long long* src = (const long long*)eiv;
            const long long* dst = src + E;
            if (q < quads) {
                longlong2 s0 = __ldcs((const longlong2*)(src + 4 * q));
                longlong2 s1 = __ldcs((const longlong2*)(src + 4 * q) + 1);
                longlong2 d0 = __ldcs((const longlong2*)(dst + 4 * q));
                longlong2 d1 = __ldcs((const longlong2*)(dst + 4 * q) + 1);
                count_rare(cls_of((int)s0.x), (int)d0.x);
                count_rare(cls_of((int)s0.y), (int)d0.y);
                count_rare(cls_of((int)s1.x), (int)d1.x);
                count_rare(cls_of((int)s1.y), (int)d1.y);
            }
            if (q == 0) {
                for (long long e = quads * 4; e < E; e++)
                    count_rare(cls_of((int)src[e]), (int)dst[e]);
            }
        }
    } else {
        // Full float fallback.
        if (g_idx64 == 0) {
            const int* src = (const int*)eiv;
            const int* dst = src + E;
            if (q < quads) {
                int4 s = __ldcs((const int4*)(src + 4 * q));
                int4 d = __ldcs((const int4*)(dst + 4 * q));
                float2 v0 = ldcg_f2(&g_xn[s.x]);
                float2 v1 = ldcg_f2(&g_xn[s.y]);
                float2 v2 = ldcg_f2(&g_xn[s.z]);
                float2 v3 = ldcg_f2(&g_xn[s.w]);
                red_add_f32x2(&g_agg[d.x], v0.x, v0.y);
                red_add_f32x2(&g_agg[d.y], v1.x, v1.y);
                red_add_f32x2(&g_agg[d.z], v2.x, v2.y);
                red_add_f32x2(&g_agg[d.w], v3.x, v3.y);
            }
            if (q == 0) {
                for (long long e = quads * 4; e < E; e++) {
                    float2 v = ldcg_f2(&g_xn[src[e]]);
                    red_add_f32x2(&g_agg[dst[e]], v.x, v.y);
                }
            }
        } else {
            const long long* src = (const long long*)eiv;
            const long long* dst = src + E;
            if (q < quads) {
                longlong2 s0 = __ldcs((const longlong2*)(src + 4 * q));
                longlong2 s1 = __ldcs((const longlong2*)(src + 4 * q) + 1);
                longlong2 d0 = __ldcs((const longlong2*)(dst + 4 * q));
                longlong2 d1 = __ldcs((const longlong2*)(dst + 4 * q) + 1);
                float2 v0 = ldcg_f2(&g_xn[(int)s0.x]);
                float2 v1 = ldcg_f2(&g_xn[(int)s0.y]);
                float2 v2 = ldcg_f2(&g_xn[(int)s1.x]);
                float2 v3 = ldcg_f2(&g_xn[(int)s1.y]);
                red_add_f32x2(&g_agg[(int)d0.x], v0.x, v0.y);
                red_add_f32x2(&g_agg[(int)d0.y], v1.x, v1.y);
                red_add_f32x2(&g_agg[(int)d1.x], v2.x, v2.y);
                red_add_f32x2(&g_agg[(int)d1.y], v3.x, v3.y);
            }
            if (q == 0) {
                for (long long e = quads * 4; e < E; e++) {
                    float2 v = ldcg_f2(&g_xn[(int)src[e]]);
                    red_add_f32x2(&g_agg[(int)dst[e]], v.x, v.y);
                }
            }
        }
    }
}

// ---------------------------------------------------------------------------
// Kernel 4: final. Clean mode: agg = (cntA, deg - cntA - cnt2) — exact
// integers matching the reference's exact sums of 1.0f (cnt arrays are all
// zero in the expected degree-only case). Fallback: read float g_agg.
// ---------------------------------------------------------------------------
__global__ void k_final(const float* __restrict__ W,
                        const float* __restrict__ fw,
                        float2* __restrict__ out, int Npairs) {
    int i = blockIdx.x * blockDim.x + threadIdx.x;
    float w00 = W[0], w01 = W[1], w10 = W[2], w11 = W[3];
    float f0 = fw[0], f1 = fw[1];
    PDL_WAIT();
    if (i >= Npairs) return;

    float4 a;
    if (g_notclean == 0) {
        float deg0 = g_aggd[2 * i].z;
        float deg1 = g_aggd[2 * i + 1].z;
        uint2 cA = ((const uint2*)g_cntA)[i];
        uint2 c2 = ((const uint2*)g_cntB)[i];
        float a0 = (float)cA.x;
        float a2 = (float)cA.y;
        a = make_float4(a0, deg0 - a0 - (float)c2.x,
                        a2, deg1 - a2 - (float)c2.y);
    } else {
        a = ((const float4*)g_agg)[i];
    }
    float y0 = fmaxf(fmaf(a.y, w10, a.x * w00), 0.0f);
    float y1 = fmaxf(fmaf(a.y, w11, a.x * w01), 0.0f);
    float y2 = fmaxf(fmaf(a.w, w10, a.z * w00), 0.0f);
    float y3 = fmaxf(fmaf(a.w, w11, a.z * w01), 0.0f);
    float s0 = fmaf(y1, f1, y0 * f0);
    float s1 = fmaf(y3, f1, y2 * f0);
    out[i] = make_float2(1.0f / (1.0f + expf(-s0)),
                         1.0f / (1.0f + expf(-s1)));
}

// ---------------------------------------------------------------------------
// Launch: init -> scatter(v4+deg) -> mid(classify) -> scatter2(tiered) ->
// final, all under PDL. Graph-capturable, allocation-free.
// ---------------------------------------------------------------------------
extern "C" void kernel_launch(void* const* d_in, const int* in_sizes, int n_in,
                              void* d_out, int out_size) {
    const float* x  = (const float*)d_in[0];
    const void*  ei = (const void*)d_in[1];
    const float* W  = (const float*)d_in[2];
    const float* fw = (const float*)d_in[3];
    float2* out = (float2*)d_out;

    int N = in_sizes[0] / 2;          // 1,000,000 (divisible by 4)
    int Npairs = N / 2;
    int Nquads = N / 4;
    long long E = (long long)in_sizes[1] / 2;
    long long equads = E >> 2;

    const int TB = 256;
    int nb_pairs = (Npairs + TB - 1) / TB;
    int nb_quads = (Nquads + TB - 1) / TB;
    int nb_scatter = (int)((equads + TB - 1) / TB);

    cudaLaunchAttribute attr[1];
    attr[0].id = cudaLaunchAttributeProgrammaticStreamSerialization;
    attr[0].val.programmaticStreamSerializationAllowed = 1;

    cudaLaunchConfig_t cfg = {};
    cfg.blockDim = dim3(TB, 1, 1);
    cfg.dynamicSmemBytes = 0;
    cfg.stream = 0;
    cfg.attrs = attr;
    cfg.numAttrs = 1;

    cfg.gridDim = dim3(nb_pairs, 1, 1);
    cudaLaunchKernelEx(&cfg, k_init, (const float4*)x, Npairs, N,
                       (const long long*)ei, E);

    cfg.gridDim = dim3(nb_scatter, 1, 1);
    cudaLaunchKernelEx(&cfg, k_scatter, (const void*)ei, E);

    cfg.gridDim = dim3(nb_quads, 1, 1);
    cudaLaunchKernelEx(&cfg, k_mid, W, Nquads);

    cfg.gridDim = dim3(nb_scatter, 1, 1);
    cudaLaunchKernelEx(&cfg, k_scatter2, (const void*)ei, E);

    cfg.gridDim = dim3(nb_pairs, 1, 1);
    cudaLaunchKernelEx(&cfg, k_final, W, fw, out, Npairs);

    (void)n_in; (void)out_size;
}

// round 13
// speedup vs baseline: 1.9530x; 1.1654x over previous
#include <cuda_runtime.h>
#include <math.h>

// ---------------------------------------------------------------------------
// Scratch. N = 1,000,000 fits in 1<<20.
// ---------------------------------------------------------------------------
#define MAXN (1 << 20)
__device__ float4        g_aggd[MAXN];        // pass1: (sum_x, sum_y, degree, 0)
__device__ float2        g_xn[MAXN];          // node state
__device__ float2        g_agg[MAXN];         // pass2 float fallback accumulator
__device__ unsigned int  g_cntA[MAXN];        // pass2: count of class-0 ((1,0)) sources
__device__ unsigned int  g_cntB[MAXN];        // pass2: count of class-2 ((0,0)) sources
__device__ unsigned char g_clsp[MAXN / 4];    // 2-bit class per node, packed 4/byte
__device__ int           g_idx64;             // 1 if edge_index is int64
__device__ int           g_notclean;          // 1 if any node is class 3 (general)
__device__ int           g_anyAB;             // 1 if any node is class 0 or 2

#define EPSF 1e-15f

#define PDL_WAIT()    asm volatile("griddepcontrol.wait;" ::: "memory")
#define PDL_TRIGGER() asm volatile("griddepcontrol.launch_dependents;" ::: "memory")

__device__ __forceinline__ void red_add_f32x4(float4* p, float a, float b,
                                              float c, float d) {
    asm volatile("red.global.add.v4.f32 [%0], {%1, %2, %3, %4};"
                 :: "l"(p), "f"(a), "f"(b), "f"(c), "f"(d)
                 : "memory");
}
__device__ __forceinline__ void red_add_f32x2(float2* p, float vx, float vy) {
    asm volatile("red.global.add.v2.f32 [%0], {%1, %2};"
                 :: "l"(p), "f"(vx), "f"(vy)
                 : "memory");
}
__device__ __forceinline__ void red_add_u32(unsigned int* p, unsigned int v) {
    asm volatile("red.global.add.u32 [%0], %1;"
                 :: "l"(p), "r"(v)
                 : "memory");
}
__device__ __forceinline__ float2 ldcg_f2(const float2* p) {
    float2 r;
    asm volatile("ld.global.cg.v2.f32 {%0, %1}, [%2];"
                 : "=f"(r.x), "=f"(r.y) : "l"(p));
    return r;
}

// ---------------------------------------------------------------------------
// Kernel 1: normalize x into g_xn (2 nodes/thread), zero g_aggd, detect dtype.
// ---------------------------------------------------------------------------
__global__ void k_init(const float4* __restrict__ x, int Npairs, int N,
                       const long long* __restrict__ ei, long long n_words) {
    PDL_TRIGGER();
    int i = blockIdx.x * blockDim.x + threadIdx.x;
    if (i < Npairs) {
        float4 v = x[i];
        float inv0 = 1.0f / (sqrtf(v.x * v.x + v.y * v.y) + EPSF);
        float inv1 = 1.0f / (sqrtf(v.z * v.z + v.w * v.w) + EPSF);
        ((float4*)g_xn)[i] = make_float4(v.x * inv0, v.y * inv0,
                                         v.z * inv1, v.w * inv1);
        g_aggd[2 * i]     = make_float4(0.f, 0.f, 0.f, 0.f);
        g_aggd[2 * i + 1] = make_float4(0.f, 0.f, 0.f, 0.f);
    }
    if (blockIdx.x == 0) {
        if (threadIdx.x == 0) { g_notclean = 0; g_anyAB = 0; }
        __shared__ int bad;
        if (threadIdx.x == 0) bad = 0;
        __syncthreads();
        long long lim = n_words < 2048 ? n_words : 2048;
        int local_bad = 0;
        for (long long w = threadIdx.x; w < lim; w += blockDim.x) {
            long long v = ei[w];
            if (v < 0 || v >= (long long)N) local_bad = 1;
        }
        if (local_bad) bad = 1;
        __syncthreads();
        if (threadIdx.x == 0) g_idx64 = bad ? 0 : 1;
    }
}

// ---------------------------------------------------------------------------
// Kernel 2: pass-1 scatter with fused degree count:
// g_aggd[dst] += (xn[src].x, xn[src].y, 1, 0) via one v4 red per edge
// (same 32B sector / wavefront cost as a v2 red). Measured-best shape:
// one quad per thread, __ldcs index loads, L2-only gathers.
// ---------------------------------------------------------------------------
__global__ void __launch_bounds__(256) k_scatter(const void* __restrict__ eiv, long long E) {
    PDL_TRIGGER();
    long long q = (long long)blockIdx.x * blockDim.x + threadIdx.x;
    long long quads = E >> 2;

    int4 s = make_int4(0, 0, 0, 0), d = make_int4(0, 0, 0, 0);
    if (q < quads) {
        const int* src32 = (const int*)eiv;
        s = __ldcs((const int4*)(src32 + 4 * q));
        d = __ldcs((const int4*)(src32 + E + 4 * q));
    }

    PDL_WAIT();

    if (g_idx64 == 0) {
        const int* src = (const int*)eiv;
        const int* dst = src + E;
        if (q < quads) {
            float2 v0 = ldcg_f2(&g_xn[s.x]);
            float2 v1 = ldcg_f2(&g_xn[s.y]);
            float2 v2 = ldcg_f2(&g_xn[s.z]);
            float2 v3 = ldcg_f2(&g_xn[s.w]);
            red_add_f32x4(&g_aggd[d.x], v0.x, v0.y, 1.0f, 0.0f);
            red_add_f32x4(&g_aggd[d.y], v1.x, v1.y, 1.0f, 0.0f);
            red_add_f32x4(&g_aggd[d.z], v2.x, v2.y, 1.0f, 0.0f);
            red_add_f32x4(&g_aggd[d.w], v3.x, v3.y, 1.0f, 0.0f);
        }
        if (q == 0) {
            for (long long e = quads * 4; e < E; e++) {
                float2 v = ldcg_f2(&g_xn[src[e]]);
                red_add_f32x4(&g_aggd[dst[e]], v.x, v.y, 1.0f, 0.0f);
            }
        }
    } else {
        const long long* src = (const long long*)eiv;
        const long long* dst = src + E;
        if (q < quads) {
            longlong2 s0 = __ldcs((const longlong2*)(src + 4 * q));
            longlong2 s1 = __ldcs((const longlong2*)(src + 4 * q) + 1);
            longlong2 d0 = __ldcs((const longlong2*)(dst + 4 * q));
            longlong2 d1 = __ldcs((const longlong2*)(dst + 4 * q) + 1);
            float2 v0 = ldcg_f2(&g_xn[(int)s0.x]);
            float2 v1 = ldcg_f2(&g_xn[(int)s0.y]);
            float2 v2 = ldcg_f2(&g_xn[(int)s1.x]);
            float2 v3 = ldcg_f2(&g_xn[(int)s1.y]);
            red_add_f32x4(&g_aggd[(int)d0.x], v0.x, v0.y, 1.0f, 0.0f);
            red_add_f32x4(&g_aggd[(int)d0.y], v1.x, v1.y, 1.0f, 0.0f);
            red_add_f32x4(&g_aggd[(int)d1.x], v2.x, v2.y, 1.0f, 0.0f);
            red_add_f32x4(&g_aggd[(int)d1.y], v3.x, v3.y, 1.0f, 0.0f);
        }
        if (q == 0) {
            for (long long e = quads * 4; e < E; e++) {
                float2 v = ldcg_f2(&g_xn[(int)src[e]]);
                red_add_f32x4(&g_aggd[(int)dst[e]], v.x, v.y, 1.0f, 0.0f);
            }
        }
    }
}

// ---------------------------------------------------------------------------
// Kernel 3: y = relu(agg @ W), classify 4 nodes/thread:
//   class 0: (t,0), t>1e-6  -> xn=(1,0) exact     (flags g_anyAB)
//   class 1: (0,t), t>1e-6  -> xn=(0,1) exact     (expected universal case)
//   class 2: (0,0)          -> xn=(0,0)           (flags g_anyAB)
//   class 3: anything else  -> general normalize  (flags g_notclean)
// ---------------------------------------------------------------------------
__global__ void k_mid(const float* __restrict__ W, int Nquads) {
    PDL_TRIGGER();
    int i = blockIdx.x * blockDim.x + threadIdx.x;
    float w00 = W[0], w01 = W[1], w10 = W[2], w11 = W[3];
    PDL_WAIT();
    if (i >= Nquads) return;

    float xo[8];
    unsigned int clsbyte = 0;
    bool dirty = false, anyab = false;

    #pragma unroll
    for (int j = 0; j < 4; j++) {
        float4 ad = g_aggd[4 * i + j];
        float y0 = fmaf(ad.y, w10, ad.x * w00);
        float y1 = fmaf(ad.y, w11, ad.x * w01);
        float r0 = fmaxf(y0, 0.0f);
        float r1 = fmaxf(y1, 0.0f);
        unsigned int c;
        float x0, x1;
        if (r0 == 0.0f && r1 > 1e-6f) {
            c = 1u; x0 = 0.0f; x1 = 1.0f;              // (0, t/(t+eps)) == (0,1)
        } else if (r1 == 0.0f && r0 > 1e-6f) {
            c = 0u; x0 = 1.0f; x1 = 0.0f; anyab = true;
        } else if (r0 == 0.0f && r1 == 0.0f) {
            c = 2u; x0 = 0.0f; x1 = 0.0f; anyab = true;
        } else {
            c = 3u; dirty = true;
            float inv = 1.0f / (sqrtf(r0 * r0 + r1 * r1) + EPSF);
            x0 = r0 * inv; x1 = r1 * inv;
        }
        clsbyte |= c << (2 * j);
        xo[2 * j] = x0; xo[2 * j + 1] = x1;
    }

    ((float4*)g_xn)[2 * i]     = make_float4(xo[0], xo[1], xo[2], xo[3]);
    ((float4*)g_xn)[2 * i + 1] = make_float4(xo[4], xo[5], xo[6], xo[7]);
    ((float4*)g_agg)[2 * i]     = make_float4(0.f, 0.f, 0.f, 0.f);
    ((float4*)g_agg)[2 * i + 1] = make_float4(0.f, 0.f, 0.f, 0.f);
    ((uint4*)g_cntA)[i] = make_uint4(0u, 0u, 0u, 0u);
    ((uint4*)g_cntB)[i] = make_uint4(0u, 0u, 0u, 0u);
    g_clsp[i] = (unsigned char)clsbyte;
    if (dirty) g_notclean = 1;
    if (anyab) g_anyAB = 1;
}

// ---------------------------------------------------------------------------
// Kernel 2b: pass-2 scatter, tiered, GRID-STRIDE with a SMALL grid (2048
// blocks). Expected case (all nodes class 1): every block reads two flags and
// exits -> ~2-3us total (vs 35.8us of block-churn with a 31250-block grid).
// Rare cases cover all edges via the stride loop at normal LTS throughput.
// ---------------------------------------------------------------------------
__device__ __forceinline__ unsigned int cls_of(int node) {
    unsigned int b = (unsigned int)g_clsp[node >> 2];
    return (b >> ((node & 3) << 1)) & 3u;
}
__device__ __forceinline__ void count_rare(unsigned int c, int dnode) {
    if (c == 0u)      red_add_u32(&g_cntA[dnode], 1u);
    else if (c == 2u) red_add_u32(&g_cntB[dnode], 1u);
}

__global__ void __launch_bounds__(256) k_scatter2(const void* __restrict__ eiv, long long E) {
    PDL_TRIGGER();
    PDL_WAIT();
    if (g_notclean == 0 && g_anyAB == 0) return;   // degree-only: nothing to do

    long long tid    = (long long)blockIdx.x * blockDim.x + threadIdx.x;
    long long stride = (long long)gridDim.x * blockDim.x;
    long long quads  = E >> 2;

    if (g_notclean == 0) {
        // Rare-class count path.
        if (g_idx64 == 0) {
            const int* src = (const int*)eiv;
            const int* dst = src + E;
            for (long long q = tid; q < quads; q += stride) {
                int4 s = __ldcs((const int4*)(src + 4 * q));
                int4 d = __ldcs((const int4*)(dst + 4 * q));
                count_rare(cls_of(s.x), d.x);
                count_rare(cls_of(s.y), d.y);
                count_rare(cls_of(s.z), d.z);
                count_rare(cls_of(s.w), d.w);
            }
            if (tid == 0) {
                for (long long e = quads * 4; e < E; e++)
                    count_rare(cls_of(src[e]), dst[e]);
            }
        } else {
            const long long* src = (const long long*)eiv;
            const long long* dst = src + E;
            for (long long q = tid; q < quads; q += stride) {
                longlong2 s0 = __ldcs((const longlong2*)(src + 4 * q));
                longlong2 s1 = __ldcs((const longlong2*)(src + 4 * q) + 1);
                longlong2 d0 = __ldcs((const longlong2*)(dst + 4 * q));
                longlong2 d1 = __ldcs((const longlong2*)(dst + 4 * q) + 1);
                count_rare(cls_of((int)s0.x), (int)d0.x);
                count_rare(cls_of((int)s0.y), (int)d0.y);
                count_rare(cls_of((int)s1.x), (int)d1.x);
                count_rare(cls_of((int)s1.y), (int)d1.y);
            }
            if (tid == 0) {
                for (long long e = quads * 4; e < E; e++)
                    count_rare(cls_of((int)src[e]), (int)dst[e]);
            }
        }
    } else {
        // Full float fallback.
        if (g_idx64 == 0) {
            const int* src = (const int*)eiv;
            const int* dst = src + E;
            for (long long q = tid; q < quads; q += stride) {
                int4 s = __ldcs((const int4*)(src + 4 * q));
                int4 d = __ldcs((const int4*)(dst + 4 * q));
                float2 v0 = ldcg_f2(&g_xn[s.x]);
                float2 v1 = ldcg_f2(&g_xn[s.y]);
                float2 v2 = ldcg_f2(&g_xn[s.z]);
                float2 v3 = ldcg_f2(&g_xn[s.w]);
                red_add_f32x2(&g_agg[d.x], v0.x, v0.y);
                red_add_f32x2(&g_agg[d.y], v1.x, v1.y);
                red_add_f32x2(&g_agg[d.z], v2.x, v2.y);
                red_add_f32x2(&g_agg[d.w], v3.x, v3.y);
            }
            if (tid == 0) {
                for (long long e = quads * 4; e < E; e++) {
                    float2 v = ldcg_f2(&g_xn[src[e]]);
                    red_add_f32x2(&g_agg[dst[e]], v.x, v.y);
                }
            }
        } else {
            const long long* src = (const long long*)eiv;
            const long long* dst = src + E;
            for (long long q = tid; q < quads; q += stride) {
                longlong2 s0 = __ldcs((const longlong2*)(src + 4 * q));
                longlong2 s1 = __ldcs((const longlong2*)(src + 4 * q) + 1);
                longlong2 d0 = __ldcs((const longlong2*)(dst + 4 * q));
                longlong2 d1 = __ldcs((const longlong2*)(dst + 4 * q) + 1);
                float2 v0 = ldcg_f2(&g_xn[(int)s0.x]);
                float2 v1 = ldcg_f2(&g_xn[(int)s0.y]);
                float2 v2 = ldcg_f2(&g_xn[(int)s1.x]);
                float2 v3 = ldcg_f2(&g_xn[(int)s1.y]);
                red_add_f32x2(&g_agg[(int)d0.x], v0.x, v0.y);
                red_add_f32x2(&g_agg[(int)d0.y], v1.x, v1.y);
                red_add_f32x2(&g_agg[(int)d1.x], v2.x, v2.y);
                red_add_f32x2(&g_agg[(int)d1.y], v3.x, v3.y);
            }
            if (tid == 0) {
                for (long long e = quads * 4; e < E; e++) {
                    float2 v = ldcg_f2(&g_xn[(int)src[e]]);
                    red_add_f32x2(&g_agg[(int)dst[e]], v.x, v.y);
                }
            }
        }
    }
}

// ---------------------------------------------------------------------------
// Kernel 4: final. Clean mode: agg = (cntA, deg - cntA - cnt2) — exact
// integers matching the reference's exact sums of 1.0f. Fallback: float g_agg.
// ---------------------------------------------------------------------------
__global__ void k_final(const float* __restrict__ W,
                        const float* __restrict__ fw,
                        float2* __restrict__ out, int Npairs) {
    int i = blockIdx.x * blockDim.x + threadIdx.x;
    float w00 = W[0], w01 = W[1], w10 = W[2], w11 = W[3];
    float f0 = fw[0], f1 = fw[1];
    PDL_WAIT();
    if (i >= Npairs) return;

    float4 a;
    if (g_notclean == 0) {
        float deg0 = g_aggd[2 * i].z;
        float deg1 = g_aggd[2 * i + 1].z;
        uint2 cA = ((const uint2*)g_cntA)[i];
        uint2 c2 = ((const uint2*)g_cntB)[i];
        float a0 = (float)cA.x;
        float a2 = (float)cA.y;
        a = make_float4(a0, deg0 - a0 - (float)c2.x,
                        a2, deg1 - a2 - (float)c2.y);
    } else {
        a = ((const float4*)g_agg)[i];
    }
    float y0 = fmaxf(fmaf(a.y, w10, a.x * w00), 0.0f);
    float y1 = fmaxf(fmaf(a.y, w11, a.x * w01), 0.0f);
    float y2 = fmaxf(fmaf(a.w, w10, a.z * w00), 0.0f);
    float y3 = fmaxf(fmaf(a.w, w11, a.z * w01), 0.0f);
    float s0 = fmaf(y1, f1, y0 * f0);
    float s1 = fmaf(y3, f1, y2 * f0);
    out[i] = make_float2(1.0f / (1.0f + expf(-s0)),
                         1.0f / (1.0f + expf(-s1)));
}

// ---------------------------------------------------------------------------
// Launch: init -> scatter(v4+deg) -> mid(classify) -> scatter2(small grid,
// tiered) -> final, all under PDL. Graph-capturable, allocation-free.
// ---------------------------------------------------------------------------
extern "C" void kernel_launch(void* const* d_in, const int* in_sizes, int n_in,
                              void* d_out, int out_size) {
    const float* x  = (const float*)d_in[0];
    const void*  ei = (const void*)d_in[1];
    const float* W  = (const float*)d_in[2];
    const float* fw = (const float*)d_in[3];
    float2* out = (float2*)d_out;

    int N = in_sizes[0] / 2;          // 1,000,000 (divisible by 4)
    int Npairs = N / 2;
    int Nquads = N / 4;
    long long E = (long long)in_sizes[1] / 2;
    long long equads = E >> 2;

    const int TB = 256;
    int nb_pairs = (Npairs + TB - 1) / TB;
    int nb_quads = (Nquads + TB - 1) / TB;
    int nb_scatter = (int)((equads + TB - 1) / TB);
    const int SC2_BLOCKS = 2048;      // small grid: fast exit on expected path

    cudaLaunchAttribute attr[1];
    attr[0].id = cudaLaunchAttributeProgrammaticStreamSerialization;
    attr[0].val.programmaticStreamSerializationAllowed = 1;

    cudaLaunchConfig_t cfg = {};
    cfg.blockDim = dim3(TB, 1, 1);
    cfg.dynamicSmemBytes = 0;
    cfg.stream = 0;
    cfg.attrs = attr;
    cfg.numAttrs = 1;

    cfg.gridDim = dim3(nb_pairs, 1, 1);
    cudaLaunchKernelEx(&cfg, k_init, (const float4*)x, Npairs, N,
                       (const long long*)ei, E);

    cfg.gridDim = dim3(nb_scatter, 1, 1);
    cudaLaunchKernelEx(&cfg, k_scatter, (const void*)ei, E);

    cfg.gridDim = dim3(nb_quads, 1, 1);
    cudaLaunchKernelEx(&cfg, k_mid, W, Nquads);

    cfg.gridDim = dim3(SC2_BLOCKS, 1, 1);
    cudaLaunchKernelEx(&cfg, k_scatter2, (const void*)ei, E);

    cfg.gridDim = dim3(nb_pairs, 1, 1);
    cudaLaunchKernelEx(&cfg, k_final, W, fw, out, Npairs);

    (void)n_in; (void)out_size;
}

// round 14
// speedup vs baseline: 1.9840x; 1.0159x over previous
#include <cuda_runtime.h>
#include <math.h>

// ---------------------------------------------------------------------------
// Scratch. N = 1,000,000 fits in 1<<20.
// ---------------------------------------------------------------------------
#define MAXN (1 << 20)
__device__ float4        g_aggd[MAXN];        // pass1: (sum_x, sum_y, degree, 0)
__device__ float2        g_xn[MAXN];          // node state
__device__ float2        g_agg[MAXN];         // pass2 float fallback accumulator
__device__ unsigned int  g_cntA[MAXN];        // pass2: count of class-0 ((1,0)) sources
__device__ unsigned int  g_cntB[MAXN];        // pass2: count of class-2 ((0,0)) sources
__device__ unsigned char g_clsp[MAXN / 4];    // 2-bit class per node, packed 4/byte
__device__ int           g_idx64;             // 1 if edge_index is int64
__device__ int           g_notclean;          // 1 if any node is class 3 (general)
__device__ int           g_anyAB;             // 1 if any node is class 0 or 2

#define EPSF 1e-15f

#define PDL_WAIT()    asm volatile("griddepcontrol.wait;" ::: "memory")
#define PDL_TRIGGER() asm volatile("griddepcontrol.launch_dependents;" ::: "memory")

__device__ __forceinline__ void red_add_f32x4(float4* p, float a, float b,
                                              float c, float d) {
    asm volatile("red.global.add.v4.f32 [%0], {%1, %2, %3, %4};"
                 :: "l"(p), "f"(a), "f"(b), "f"(c), "f"(d)
                 : "memory");
}
__device__ __forceinline__ void red_add_f32x2(float2* p, float vx, float vy) {
    asm volatile("red.global.add.v2.f32 [%0], {%1, %2};"
                 :: "l"(p), "f"(vx), "f"(vy)
                 : "memory");
}
__device__ __forceinline__ void red_add_u32(unsigned int* p, unsigned int v) {
    asm volatile("red.global.add.u32 [%0], %1;"
                 :: "l"(p), "r"(v)
                 : "memory");
}
__device__ __forceinline__ float2 ldcg_f2(const float2* p) {
    float2 r;
    asm volatile("ld.global.cg.v2.f32 {%0, %1}, [%2];"
                 : "=f"(r.x), "=f"(r.y) : "l"(p));
    return r;
}

// Shared classification: from raw sums (a0,a1) compute class + normalized x.
__device__ __forceinline__ unsigned int classify(float a0, float a1,
                                                 float w00, float w01,
                                                 float w10, float w11,
                                                 float& x0, float& x1) {
    float y0 = fmaf(a1, w10, a0 * w00);
    float y1 = fmaf(a1, w11, a0 * w01);
    float r0 = fmaxf(y0, 0.0f);
    float r1 = fmaxf(y1, 0.0f);
    if (r0 == 0.0f && r1 > 1e-6f) { x0 = 0.0f; x1 = 1.0f; return 1u; }
    if (r1 == 0.0f && r0 > 1e-6f) { x0 = 1.0f; x1 = 0.0f; return 0u; }
    if (r0 == 0.0f && r1 == 0.0f) { x0 = 0.0f; x1 = 0.0f; return 2u; }
    float inv = 1.0f / (sqrtf(r0 * r0 + r1 * r1) + EPSF);
    x0 = r0 * inv; x1 = r1 * inv;
    return 3u;
}

// ---------------------------------------------------------------------------
// Kernel 1: normalize x into g_xn (2 nodes/thread), zero g_aggd, detect dtype.
// ---------------------------------------------------------------------------
__global__ void k_init(const float4* __restrict__ x, int Npairs, int N,
                       const long long* __restrict__ ei, long long n_words) {
    PDL_TRIGGER();
    int i = blockIdx.x * blockDim.x + threadIdx.x;
    if (i < Npairs) {
        float4 v = x[i];
        float inv0 = 1.0f / (sqrtf(v.x * v.x + v.y * v.y) + EPSF);
        float inv1 = 1.0f / (sqrtf(v.z * v.z + v.w * v.w) + EPSF);
        ((float4*)g_xn)[i] = make_float4(v.x * inv0, v.y * inv0,
                                         v.z * inv1, v.w * inv1);
        g_aggd[2 * i]     = make_float4(0.f, 0.f, 0.f, 0.f);
        g_aggd[2 * i + 1] = make_float4(0.f, 0.f, 0.f, 0.f);
    }
    if (blockIdx.x == 0) {
        if (threadIdx.x == 0) { g_notclean = 0; g_anyAB = 0; }
        __shared__ int bad;
        if (threadIdx.x == 0) bad = 0;
        __syncthreads();
        long long lim = n_words < 2048 ? n_words : 2048;
        int local_bad = 0;
        for (long long w = threadIdx.x; w < lim; w += blockDim.x) {
            long long v = ei[w];
            if (v < 0 || v >= (long long)N) local_bad = 1;
        }
        if (local_bad) bad = 1;
        __syncthreads();
        if (threadIdx.x == 0) g_idx64 = bad ? 0 : 1;
    }
}

// ---------------------------------------------------------------------------
// Kernel 2: pass-1 scatter with fused degree count:
// g_aggd[dst] += (xn[src].x, xn[src].y, 1, 0) via one v4 red per edge.
// Measured-best shape: one quad per thread, __ldcs index loads, L2 gathers.
// ---------------------------------------------------------------------------
__global__ void __launch_bounds__(256) k_scatter(const void* __restrict__ eiv, long long E) {
    PDL_TRIGGER();
    long long q = (long long)blockIdx.x * blockDim.x + threadIdx.x;
    long long quads = E >> 2;

    int4 s = make_int4(0, 0, 0, 0), d = make_int4(0, 0, 0, 0);
    if (q < quads) {
        const int* src32 = (const int*)eiv;
        s = __ldcs((const int4*)(src32 + 4 * q));
        d = __ldcs((const int4*)(src32 + E + 4 * q));
    }

    PDL_WAIT();

    if (g_idx64 == 0) {
        const int* src = (const int*)eiv;
        const int* dst = src + E;
        if (q < quads) {
            float2 v0 = ldcg_f2(&g_xn[s.x]);
            float2 v1 = ldcg_f2(&g_xn[s.y]);
            float2 v2 = ldcg_f2(&g_xn[s.z]);
            float2 v3 = ldcg_f2(&g_xn[s.w]);
            red_add_f32x4(&g_aggd[d.x], v0.x, v0.y, 1.0f, 0.0f);
            red_add_f32x4(&g_aggd[d.y], v1.x, v1.y, 1.0f, 0.0f);
            red_add_f32x4(&g_aggd[d.z], v2.x, v2.y, 1.0f, 0.0f);
            red_add_f32x4(&g_aggd[d.w], v3.x, v3.y, 1.0f, 0.0f);
        }
        if (q == 0) {
            for (long long e = quads * 4; e < E; e++) {
                float2 v = ldcg_f2(&g_xn[src[e]]);
                red_add_f32x4(&g_aggd[dst[e]], v.x, v.y, 1.0f, 0.0f);
            }
        }
    } else {
        const long long* src = (const long long*)eiv;
        const long long* dst = src + E;
        if (q < quads) {
            longlong2 s0 = __ldcs((const longlong2*)(src + 4 * q));
            longlong2 s1 = __ldcs((const longlong2*)(src + 4 * q) + 1);
            longlong2 d0 = __ldcs((const longlong2*)(dst + 4 * q));
            longlong2 d1 = __ldcs((const longlong2*)(dst + 4 * q) + 1);
            float2 v0 = ldcg_f2(&g_xn[(int)s0.x]);
            float2 v1 = ldcg_f2(&g_xn[(int)s0.y]);
            float2 v2 = ldcg_f2(&g_xn[(int)s1.x]);
            float2 v3 = ldcg_f2(&g_xn[(int)s1.y]);
            red_add_f32x4(&g_aggd[(int)d0.x], v0.x, v0.y, 1.0f, 0.0f);
            red_add_f32x4(&g_aggd[(int)d0.y], v1.x, v1.y, 1.0f, 0.0f);
            red_add_f32x4(&g_aggd[(int)d1.x], v2.x, v2.y, 1.0f, 0.0f);
            red_add_f32x4(&g_aggd[(int)d1.y], v3.x, v3.y, 1.0f, 0.0f);
        }
        if (q == 0) {
            for (long long e = quads * 4; e < E; e++) {
                float2 v = ldcg_f2(&g_xn[(int)src[e]]);
                red_add_f32x4(&g_aggd[(int)dst[e]], v.x, v.y, 1.0f, 0.0f);
            }
        }
    }
}

// ---------------------------------------------------------------------------
// Kernel 3: CLASSIFY-ONLY. Read g_aggd (16MB), write packed classes (256KB)
// + flags. The g_xn rewrite / g_agg / cnt zeroing are dead work in the
// expected clean case and are deferred to flag-gated k_prep.
// ---------------------------------------------------------------------------
__global__ void k_mid(const float* __restrict__ W, int Nquads) {
    PDL_TRIGGER();
    int i = blockIdx.x * blockDim.x + threadIdx.x;
    float w00 = W[0], w01 = W[1], w10 = W[2], w11 = W[3];
    PDL_WAIT();
    if (i >= Nquads) return;

    unsigned int clsbyte = 0;
    bool dirty = false, anyab = false;

    #pragma unroll
    for (int j = 0; j < 4; j++) {
        float4 ad = g_aggd[4 * i + j];
        float x0, x1;
        unsigned int c = classify(ad.x, ad.y, w00, w01, w10, w11, x0, x1);
        clsbyte |= c << (2 * j);
        if (c == 3u) dirty = true;
        else if (c != 1u) anyab = true;
    }

    g_clsp[i] = (unsigned char)clsbyte;
    if (dirty) g_notclean = 1;
    if (anyab) g_anyAB = 1;
}

// ---------------------------------------------------------------------------
// Kernel 3b: flag-gated prep for the RARE paths. Expected case: read two
// flags and exit (~2us at 1024 blocks). Rare case: recompute g_xn from
// g_aggd, zero g_agg and the count arrays, grid-stride.
// ---------------------------------------------------------------------------
__global__ void __launch_bounds__(256) k_prep(const float* __restrict__ W, int Nquads) {
    PDL_TRIGGER();
    PDL_WAIT();
    if (g_notclean == 0 && g_anyAB == 0) return;

    float w00 = W[0], w01 = W[1], w10 = W[2], w11 = W[3];
    int stride = gridDim.x * blockDim.x;
    for (int i = blockIdx.x * blockDim.x + threadIdx.x; i < Nquads; i += stride) {
        float xo[8];
        #pragma unroll
        for (int j = 0; j < 4; j++) {
            float4 ad = g_aggd[4 * i + j];
            classify(ad.x, ad.y, w00, w01, w10, w11, xo[2 * j], xo[2 * j + 1]);
        }
        ((float4*)g_xn)[2 * i]     = make_float4(xo[0], xo[1], xo[2], xo[3]);
        ((float4*)g_xn)[2 * i + 1] = make_float4(xo[4], xo[5], xo[6], xo[7]);
        ((float4*)g_agg)[2 * i]     = make_float4(0.f, 0.f, 0.f, 0.f);
        ((float4*)g_agg)[2 * i + 1] = make_float4(0.f, 0.f, 0.f, 0.f);
        ((uint4*)g_cntA)[i] = make_uint4(0u, 0u, 0u, 0u);
        ((uint4*)g_cntB)[i] = make_uint4(0u, 0u, 0u, 0u);
    }
}

// ---------------------------------------------------------------------------
// Kernel 2b: pass-2 scatter, tiered, grid-stride small grid. Expected case:
// read flags, exit. Rare clean: count rare-class sources. Class-3: full
// float fallback.
// ---------------------------------------------------------------------------
__device__ __forceinline__ unsigned int cls_of(int node) {
    unsigned int b = (unsigned int)g_clsp[node >> 2];
    return (b >> ((node & 3) << 1)) & 3u;
}
__device__ __forceinline__ void count_rare(unsigned int c, int dnode) {
    if (c == 0u)      red_add_u32(&g_cntA[dnode], 1u);
    else if (c == 2u) red_add_u32(&g_cntB[dnode], 1u);
}

__global__ void __launch_bounds__(256) k_scatter2(const void* __restrict__ eiv, long long E) {
    PDL_TRIGGER();
    PDL_WAIT();
    if (g_notclean == 0 && g_anyAB == 0) return;   // degree-only: nothing to do

    long long tid    = (long long)blockIdx.x * blockDim.x + threadIdx.x;
    long long stride = (long long)gridDim.x * blockDim.x;
    long long quads  = E >> 2;

    if (g_notclean == 0) {
        if (g_idx64 == 0) {
            const int* src = (const int*)eiv;
            const int* dst = src + E;
            for (long long q = tid; q < quads; q += stride) {
                int4 s = __ldcs((const int4*)(src + 4 * q));
                int4 d = __ldcs((const int4*)(dst + 4 * q));
                count_rare(cls_of(s.x), d.x);
                count_rare(cls_of(s.y), d.y);
                count_rare(cls_of(s.z), d.z);
                count_rare(cls_of(s.w), d.w);
            }
            if (tid == 0) {
                for (long long e = quads * 4; e < E; e++)
                    count_rare(cls_of(src[e]), dst[e]);
            }
        } else {
            const long long* src = (const long long*)eiv;
            const long long* dst = src + E;
            for (long long q = tid; q < quads; q += stride) {
                longlong2 s0 = __ldcs((const longlong2*)(src + 4 * q));
                longlong2 s1 = __ldcs((const longlong2*)(src + 4 * q) + 1);
                longlong2 d0 = __ldcs((const longlong2*)(dst + 4 * q));
                longlong2 d1 = __ldcs((const longlong2*)(dst + 4 * q) + 1);
                count_rare(cls_of((int)s0.x), (int)d0.x);
                count_rare(cls_of((int)s0.y), (int)d0.y);
                count_rare(cls_of((int)s1.x), (int)d1.x);
                count_rare(cls_of((int)s1.y), (int)d1.y);
            }
            if (tid == 0) {
                for (long long e = quads * 4; e < E; e++)
                    count_rare(cls_of((int)src[e]), (int)dst[e]);
            }
        }
    } else {
        if (g_idx64 == 0) {
            const int* src = (const int*)eiv;
            const int* dst = src + E;
            for (long long q = tid; q < quads; q += stride) {
                int4 s = __ldcs((const int4*)(src + 4 * q));
                int4 d = __ldcs((const int4*)(dst + 4 * q));
                float2 v0 = ldcg_f2(&g_xn[s.x]);
                float2 v1 = ldcg_f2(&g_xn[s.y]);
                float2 v2 = ldcg_f2(&g_xn[s.z]);
                float2 v3 = ldcg_f2(&g_xn[s.w]);
                red_add_f32x2(&g_agg[d.x], v0.x, v0.y);
                red_add_f32x2(&g_agg[d.y], v1.x, v1.y);
                red_add_f32x2(&g_agg[d.z], v2.x, v2.y);
                red_add_f32x2(&g_agg[d.w], v3.x, v3.y);
            }
            if (tid == 0) {
                for (long long e = quads * 4; e < E; e++) {
                    float2 v = ldcg_f2(&g_xn[src[e]]);
                    red_add_f32x2(&g_agg[dst[e]], v.x, v.y);
                }
            }
        } else {
            const long long* src = (const long long*)eiv;
            const long long* dst = src + E;
            for (long long q = tid; q < quads; q += stride) {
                longlong2 s0 = __ldcs((const longlong2*)(src + 4 * q));
                longlong2 s1 = __ldcs((const longlong2*)(src + 4 * q) + 1);
                longlong2 d0 = __ldcs((const longlong2*)(dst + 4 * q));
                longlong2 d1 = __ldcs((const longlong2*)(dst + 4 * q) + 1);
                float2 v0 = ldcg_f2(&g_xn[(int)s0.x]);
                float2 v1 = ldcg_f2(&g_xn[(int)s0.y]);
                float2 v2 = ldcg_f2(&g_xn[(int)s1.x]);
                float2 v3 = ldcg_f2(&g_xn[(int)s1.y]);
                red_add_f32x2(&g_agg[(int)d0.x], v0.x, v0.y);
                red_add_f32x2(&g_agg[(int)d0.y], v1.x, v1.y);
                red_add_f32x2(&g_agg[(int)d1.x], v2.x, v2.y);
                red_add_f32x2(&g_agg[(int)d1.y], v3.x, v3.y);
            }
            if (tid == 0) {
                for (long long e = quads * 4; e < E; e++) {
                    float2 v = ldcg_f2(&g_xn[(int)src[e]]);
                    red_add_f32x2(&g_agg[(int)dst[e]], v.x, v.y);
                }
            }
        }
    }
}

// ---------------------------------------------------------------------------
// Kernel 4: final. Three tiers:
//   all-class-1 (expected): agg = (0, deg)        (reads only g_aggd)
//   clean w/ rare classes:  agg = (cntA, deg - cntA - cnt2)
//   class-3 present:        float g_agg fallback
// ---------------------------------------------------------------------------
__global__ void k_final(const float* __restrict__ W,
                        const float* __restrict__ fw,
                        float2* __restrict__ out, int Npairs) {
    int i = blockIdx.x * blockDim.x + threadIdx.x;
    float w00 = W[0], w01 = W[1], w10 = W[2], w11 = W[3];
    float f0 = fw[0], f1 = fw[1];
    PDL_WAIT();
    if (i >= Npairs) return;

    float4 a;
    if (g_notclean == 0) {
        float deg0 = g_aggd[2 * i].z;
        float deg1 = g_aggd[2 * i + 1].z;
        if (g_anyAB == 0) {
            a = make_float4(0.0f, deg0, 0.0f, deg1);
        } else {
            uint2 cA = ((const uint2*)g_cntA)[i];
            uint2 c2 = ((const uint2*)g_cntB)[i];
            float a0 = (float)cA.x;
            float a2 = (float)cA.y;
            a = make_float4(a0, deg0 - a0 - (float)c2.x,
                            a2, deg1 - a2 - (float)c2.y);
        }
    } else {
        a = ((const float4*)g_agg)[i];
    }
    float y0 = fmaxf(fmaf(a.y, w10, a.x * w00), 0.0f);
    float y1 = fmaxf(fmaf(a.y, w11, a.x * w01), 0.0f);
    float y2 = fmaxf(fmaf(a.w, w10, a.z * w00), 0.0f);
    float y3 = fmaxf(fmaf(a.w, w11, a.z * w01), 0.0f);
    float s0 = fmaf(y1, f1, y0 * f0);
    float s1 = fmaf(y3, f1, y2 * f0);
    out[i] = make_float2(1.0f / (1.0f + expf(-s0)),
                         1.0f / (1.0f + expf(-s1)));
}

// ---------------------------------------------------------------------------
// Launch: init -> scatter(v4+deg) -> mid(classify) -> prep(gated) ->
// scatter2(gated) -> final, all under PDL. Graph-capturable, allocation-free.
// ---------------------------------------------------------------------------
extern "C" void kernel_launch(void* const* d_in, const int* in_sizes, int n_in,
                              void* d_out, int out_size) {
    const float* x  = (const float*)d_in[0];
    const void*  ei = (const void*)d_in[1];
    const float* W  = (const float*)d_in[2];
    const float* fw = (const float*)d_in[3];
    float2* out = (float2*)d_out;

    int N = in_sizes[0] / 2;          // 1,000,000 (divisible by 4)
    int Npairs = N / 2;
    int Nquads = N / 4;
    long long E = (long long)in_sizes[1] / 2;
    long long equads = E >> 2;

    const int TB = 256;
    int nb_pairs = (Npairs + TB - 1) / TB;
    int nb_quads = (Nquads + TB - 1) / TB;
    int nb_scatter = (int)((equads + TB - 1) / TB);
    const int GATED_BLOCKS = 1024;    // small grid: fast exit on expected path

    cudaLaunchAttribute attr[1];
    attr[0].id = cudaLaunchAttributeProgrammaticStreamSerialization;
    attr[0].val.programmaticStreamSerializationAllowed = 1;

    cudaLaunchConfig_t cfg = {};
    cfg.blockDim = dim3(TB, 1, 1);
    cfg.dynamicSmemBytes = 0;
    cfg.stream = 0;
    cfg.attrs = attr;
    cfg.numAttrs = 1;

    cfg.gridDim = dim3(nb_pairs, 1, 1);
    cudaLaunchKernelEx(&cfg, k_init, (const float4*)x, Npairs, N,
                       (const long long*)ei, E);

    cfg.gridDim = dim3(nb_scatter, 1, 1);
    cudaLaunchKernelEx(&cfg, k_scatter, (const void*)ei, E);

    cfg.gridDim = dim3(nb_quads, 1, 1);
    cudaLaunchKernelEx(&cfg, k_mid, W, Nquads);

    cfg.gridDim = dim3(GATED_BLOCKS, 1, 1);
    cudaLaunchKernelEx(&cfg, k_prep, W, Nquads);

    cfg.gridDim = dim3(GATED_BLOCKS, 1, 1);
    cudaLaunchKernelEx(&cfg, k_scatter2, (const void*)ei, E);

    cfg.gridDim = dim3(nb_pairs, 1, 1);
    cudaLaunchKernelEx(&cfg, k_final, W, fw, out, Npairs);

    (void)n_in; (void)out_size;
}